// round 1
// baseline (speedup 1.0000x reference)
#include <cuda_runtime.h>
#include <math.h>
#include <stdint.h>

// ---------------------------------------------------------------------------
// InnerConvexViolationProjection — GB300 sm_103a
// 2-CTA cluster per (b,s) problem; each CTA holds 128 rows of A_w in SMEM
// (col-major, stride 129 floats => conflict-free LDS in both matvec
// directions). Partial-g / scalar exchanges via DSMEM + barrier.cluster,
// double-buffered so exactly ONE cluster sync per exchange.
// ---------------------------------------------------------------------------

#define Mm       256
#define Nn       256
#define HR       128     // rows per CTA
#define STRIDE   129     // SMEM column stride (floats), stride%32==1 -> no conflicts
#define NTH      256
#define KITERS   30
#define PITERS   5

#define MU_IN    1e-3f
#define RHO_C    1e-12f
#define FEAS_TOL 1e-7f
#define EPS_IN   1e-6f

struct Smem {
    float A[Nn * STRIDE];      // A_w half, col-major: A[j*129 + i], i in [0,128)
    float x[Nn];               // replicated iterate
    float x0[Nn];              // original x
    float d[Nn];               // power-iter v, later d = x0 - x_uvp
    float gbuf[2][2][Nn];      // [slot][rank][j] exchanged partials
    float sbuf[2][2];          // [slot][rank] exchanged scalars
    float bw[HR];              // b_w for own rows
    float part[2][HR];         // row-matvec partials (col-half h)
    float u[HR];               // own-row vector (Av / relu(r) / Ax)
    float red[NTH];            // block reduction scratch
};

__device__ __forceinline__ uint32_t smem_addr(const void* p) {
    return (uint32_t)__cvta_generic_to_shared(const_cast<void*>(p));
}
__device__ __forceinline__ uint32_t mapa_rank(uint32_t a, uint32_t rank) {
    uint32_t r;
    asm("mapa.shared::cluster.u32 %0, %1, %2;" : "=r"(r) : "r"(a), "r"(rank));
    return r;
}
__device__ __forceinline__ void st_remote_f32(uint32_t a, float v) {
    asm volatile("st.shared::cluster.f32 [%0], %1;" :: "r"(a), "f"(v) : "memory");
}
__device__ __forceinline__ void cluster_sync() {
    asm volatile("barrier.cluster.arrive.aligned;" ::: "memory");
    asm volatile("barrier.cluster.wait.aligned;"   ::: "memory");
}

// deterministic block reductions (identical in both CTAs of a cluster)
__device__ __forceinline__ float reduce_sum(float* red, int t, float v) {
    red[t] = v; __syncthreads();
    for (int s = NTH / 2; s > 0; s >>= 1) {
        if (t < s) red[t] = red[t] + red[t + s];
        __syncthreads();
    }
    float r = red[0]; __syncthreads();
    return r;
}
__device__ __forceinline__ float reduce_max(float* red, int t, float v) {
    red[t] = v; __syncthreads();
    for (int s = NTH / 2; s > 0; s >>= 1) {
        if (t < s) red[t] = fmaxf(red[t], red[t + s]);
        __syncthreads();
    }
    float r = red[0]; __syncthreads();
    return r;
}
__device__ __forceinline__ float reduce_min(float* red, int t, float v) {
    red[t] = v; __syncthreads();
    for (int s = NTH / 2; s > 0; s >>= 1) {
        if (t < s) red[t] = fminf(red[t], red[t + s]);
        __syncthreads();
    }
    float r = red[0]; __syncthreads();
    return r;
}

// r-direction partial: row i, column half h -> sum_j A[i][h*128+j] * vec[h*128+j]
// Lanes (consecutive i, uniform h) hit distinct banks; vec read as broadcast f4.
__device__ __forceinline__ float mv_rows(const float* __restrict__ A,
                                         const float* __restrict__ vec,
                                         int i, int h) {
    const float*  Ac = A + (h * HR) * STRIDE + i;
    const float4* v4 = reinterpret_cast<const float4*>(vec + h * HR);
    float acc0 = 0.f, acc1 = 0.f;
    #pragma unroll 8
    for (int k = 0; k < HR / 4; k++) {
        float4 vv = v4[k];
        acc0 = fmaf(Ac[(4 * k + 0) * STRIDE], vv.x, acc0);
        acc1 = fmaf(Ac[(4 * k + 1) * STRIDE], vv.y, acc1);
        acc0 = fmaf(Ac[(4 * k + 2) * STRIDE], vv.z, acc0);
        acc1 = fmaf(Ac[(4 * k + 3) * STRIDE], vv.w, acc1);
    }
    return acc0 + acc1;
}

// g-direction partial: column j -> sum_i A[i][j] * u[i] over own 128 rows.
// Lane addresses j*129+i => banks (i+j)%32 distinct; u read as broadcast f4.
__device__ __forceinline__ float mv_cols(const float* __restrict__ A,
                                         const float* __restrict__ u,
                                         int j) {
    const float*  Ac = A + j * STRIDE;
    const float4* u4 = reinterpret_cast<const float4*>(u);
    float acc0 = 0.f, acc1 = 0.f;
    #pragma unroll 8
    for (int k = 0; k < HR / 4; k++) {
        float4 uu = u4[k];
        acc0 = fmaf(Ac[4 * k + 0], uu.x, acc0);
        acc1 = fmaf(Ac[4 * k + 1], uu.y, acc1);
        acc0 = fmaf(Ac[4 * k + 2], uu.z, acc0);
        acc1 = fmaf(Ac[4 * k + 3], uu.w, acc1);
    }
    return acc0 + acc1;
}

__global__ void __cluster_dims__(2, 1, 1) __launch_bounds__(NTH, 1)
proj_kernel(const float* __restrict__ x_g, const float* __restrict__ A_g,
            const float* __restrict__ b_g, float* __restrict__ out_g)
{
    extern __shared__ __align__(16) unsigned char smem_raw[];
    Smem& sm = *reinterpret_cast<Smem*>(smem_raw);

    const int t    = threadIdx.x;
    const int rank = blockIdx.x & 1;         // == cluster_ctarank for (2,1,1)
    const int prob = blockIdx.x >> 1;
    const int i_   = t & (HR - 1);
    const int h_   = t >> 7;

    const uint32_t peer     = rank ^ 1;
    const uint32_t gbuf_rem = mapa_rank(smem_addr(&sm.gbuf[0][0][0]), peer);
    const uint32_t sbuf_rem = mapa_rank(smem_addr(&sm.sbuf[0][0]), peer);
    int phase = 0;

    // ---- setup: load + row-normalize own half of A, b_w; load x; init v ----
    {
        const int wid = t >> 5, lane = t & 31;
        const float* Ap = A_g + (size_t)prob * (Mm * Nn) + (size_t)rank * HR * Nn;
        for (int i = wid; i < HR; i += NTH / 32) {
            const float* arow = Ap + (size_t)i * Nn;
            float av[8];
            float ss = 0.f;
            #pragma unroll
            for (int k = 0; k < 8; k++) {
                float a = arow[lane + 32 * k];
                av[k] = a;
                ss = fmaf(a, a, ss);
            }
            #pragma unroll
            for (int o = 16; o > 0; o >>= 1) ss += __shfl_xor_sync(0xffffffffu, ss, o);
            float rn = fmaxf(sqrtf(ss), 1e-12f);
            #pragma unroll
            for (int k = 0; k < 8; k++)
                sm.A[(lane + 32 * k) * STRIDE + i] = av[k] / rn;
            if (lane == 0)
                sm.bw[i] = b_g[(size_t)prob * Mm + rank * HR + i] / rn;
        }
        float xv = x_g[(size_t)prob * Nn + t];
        sm.x[t]  = xv;
        sm.x0[t] = xv;
        sm.d[t]  = 0.0625f;   // v0 = ones/||ones|| (exact in fp32)
    }
    __syncthreads();

    // ---- power iteration: v <- normalize(A^T A v), 5 iters ----
    for (int it = 0; it < PITERS; it++) {
        // u = (A v) on own rows
        float p = mv_rows(sm.A, sm.d, i_, h_);
        sm.part[h_][i_] = p;
        __syncthreads();
        if (t < HR) sm.u[t] = sm.part[0][t] + sm.part[1][t];
        __syncthreads();
        // partial A^T u over own rows, exchange, combine in rank order
        float q = mv_cols(sm.A, sm.u, t);
        int slot = phase & 1;
        sm.gbuf[slot][rank][t] = q;
        st_remote_f32(gbuf_rem + (uint32_t)(((slot * 2 + rank) * Nn + t) * 4), q);
        cluster_sync(); phase++;
        float w = sm.gbuf[slot][0][t] + sm.gbuf[slot][1][t];
        float s = reduce_sum(sm.red, t, w * w);
        float nv = sqrtf(s) + 1e-12f;
        sm.d[t] = w / nv;
        __syncthreads();
    }

    // ---- eta = 1 / (||A v||^2 + rho) ----
    float eta;
    {
        float p = mv_rows(sm.A, sm.d, i_, h_);
        sm.part[h_][i_] = p;
        __syncthreads();
        if (t < HR) sm.u[t] = sm.part[0][t] + sm.part[1][t];
        __syncthreads();
        float uv = (t < HR) ? sm.u[t] : 0.f;
        float sown = reduce_sum(sm.red, t, uv * uv);
        int slot = phase & 1;
        if (t == 0) {
            sm.sbuf[slot][rank] = sown;
            st_remote_f32(sbuf_rem + (uint32_t)((slot * 2 + rank) * 4), sown);
        }
        cluster_sync(); phase++;
        eta = 1.0f / ((sm.sbuf[slot][0] + sm.sbuf[slot][1]) + RHO_C);
    }

    // ---- K-step UVP on tightened constraints ----
    for (int it = 0; it < KITERS; it++) {
        float p = mv_rows(sm.A, sm.x, i_, h_);
        sm.part[h_][i_] = p;
        __syncthreads();
        if (t < HR) {
            float r = (sm.part[0][t] + sm.part[1][t]) - (sm.bw[t] - MU_IN);
            sm.u[t] = fmaxf(r, 0.f);
        }
        __syncthreads();
        float q = mv_cols(sm.A, sm.u, t);
        int slot = phase & 1;
        sm.gbuf[slot][rank][t] = q;
        st_remote_f32(gbuf_rem + (uint32_t)(((slot * 2 + rank) * Nn + t) * 4), q);
        cluster_sync(); phase++;
        sm.x[t] = sm.x[t] - eta * (sm.gbuf[slot][0][t] + sm.gbuf[slot][1][t]);
        __syncthreads();
    }

    // ---- stage 2: feasibility gate + alpha line search ----
    // Ax on x_uvp
    {
        float p = mv_rows(sm.A, sm.x, i_, h_);
        sm.part[h_][i_] = p;
        __syncthreads();
        if (t < HR) sm.u[t] = sm.part[0][t] + sm.part[1][t];   // Ax (own rows)
        __syncthreads();
    }
    float viol = (t < HR) ? fmaxf(sm.u[t] - sm.bw[t], 0.f) : 0.f;
    float mvown = reduce_max(sm.red, t, viol);
    float maxviol;
    {
        int slot = phase & 1;
        if (t == 0) {
            sm.sbuf[slot][rank] = mvown;
            st_remote_f32(sbuf_rem + (uint32_t)((slot * 2 + rank) * 4), mvown);
        }
        cluster_sync(); phase++;
        maxviol = fmaxf(sm.sbuf[slot][0], sm.sbuf[slot][1]);
    }
    const bool do_alpha = (maxviol <= FEAS_TOL);

    // d = x0 - x_uvp; Ad; alpha
    sm.d[t] = sm.x0[t] - sm.x[t];
    __syncthreads();
    {
        float p = mv_rows(sm.A, sm.d, i_, h_);
        sm.part[h_][i_] = p;
        __syncthreads();
    }
    float aown = INFINITY;
    if (t < HR) {
        float ad    = sm.part[0][t] + sm.part[1][t];
        float slack = sm.bw[t] - sm.u[t];
        aown = (ad > 0.f) ? slack / (ad + 1e-12f) : INFINITY;
    }
    float amin = reduce_min(sm.red, t, aown);
    float alpha;
    {
        int slot = phase & 1;
        if (t == 0) {
            sm.sbuf[slot][rank] = amin;
            st_remote_f32(sbuf_rem + (uint32_t)((slot * 2 + rank) * 4), amin);
        }
        cluster_sync(); phase++;
        alpha = fminf(sm.sbuf[slot][0], sm.sbuf[slot][1]);
    }
    if (!isfinite(alpha)) alpha = 1.0f;
    alpha = fminf(fmaxf(alpha - EPS_IN, 0.f), 1.f);

    if (rank == 0) {
        float o = do_alpha ? (sm.x[t] + alpha * sm.d[t]) : sm.x[t];
        out_g[(size_t)prob * Nn + t] = o;
    }
}

extern "C" void kernel_launch(void* const* d_in, const int* in_sizes, int n_in,
                              void* d_out, int out_size) {
    const float* x = (const float*)d_in[0];
    const float* A = (const float*)d_in[1];
    const float* b = (const float*)d_in[2];
    float* out = (float*)d_out;

    const int nprob = in_sizes[0] / Nn;   // B*S
    cudaFuncSetAttribute(proj_kernel, cudaFuncAttributeMaxDynamicSharedMemorySize,
                         (int)sizeof(Smem));
    proj_kernel<<<nprob * 2, NTH, sizeof(Smem)>>>(x, A, b, out);
}

// round 2
// speedup vs baseline: 1.3786x; 1.3786x over previous
#include <cuda_runtime.h>
#include <math.h>
#include <stdint.h>

// ---------------------------------------------------------------------------
// InnerConvexViolationProjection — GB300 sm_103a, round 2
// 2-CTA cluster per (b,s) problem. Each CTA: 128 rows of A_w.
//  - A row-segments register-cached (64 f32/thread, 512 threads) => zero
//    SMEM A traffic in the A·x direction.
//  - SMEM copy col-major stride 132 => conflict-free LDS.128 in the A^T·u
//    direction (bank base 4j, 8-lane phases disjoint).
//  - Shuffle-based reductions (2 barriers), DSMEM double-buffered exchange,
//    one cluster sync per exchange.
// ---------------------------------------------------------------------------

#define Mm       256
#define Nn       256
#define HR       128     // rows per CTA
#define STRIDE   132     // SMEM column stride (floats); 132%32==4 -> f4-friendly
#define NTH      512
#define QC       64      // columns cached per thread (rows direction)
#define KITERS   30
#define PITERS   5

#define MU_IN    1e-3f
#define RHO_C    1e-12f
#define FEAS_TOL 1e-7f
#define EPS_IN   1e-6f

struct Smem {
    float A[Nn * STRIDE];      // A_w half, col-major: A[j*132 + i], i in [0,128)
    float x[Nn];               // replicated iterate
    float x0[Nn];              // original x
    float d[Nn];               // power-iter v, later d = x0 - x_uvp
    float gbuf[2][2][Nn];      // [slot][rank][j] exchanged partials
    float sbuf[2][2];          // [slot][rank] exchanged scalars
    float bw[HR];              // b_w for own rows
    float part[4][HR];         // row-matvec partials (col quarter h)
    float gpart[2][Nn];        // col-matvec partials (row half g)
    float u[HR];               // own-row vector (Av / relu(r) / Ax)
    float red[32];             // reduction scratch
};

__device__ __forceinline__ uint32_t smem_addr(const void* p) {
    return (uint32_t)__cvta_generic_to_shared(const_cast<void*>(p));
}
__device__ __forceinline__ uint32_t mapa_rank(uint32_t a, uint32_t rank) {
    uint32_t r;
    asm("mapa.shared::cluster.u32 %0, %1, %2;" : "=r"(r) : "r"(a), "r"(rank));
    return r;
}
__device__ __forceinline__ void st_remote_f32(uint32_t a, float v) {
    asm volatile("st.shared::cluster.f32 [%0], %1;" :: "r"(a), "f"(v) : "memory");
}
__device__ __forceinline__ void cluster_sync() {
    asm volatile("barrier.cluster.arrive.aligned;" ::: "memory");
    asm volatile("barrier.cluster.wait.aligned;"   ::: "memory");
}

// ---- shuffle-based block reductions (deterministic, 2 barriers) ----
__device__ __forceinline__ float reduce_sum(float* red, int t, float v) {
    #pragma unroll
    for (int o = 16; o > 0; o >>= 1) v += __shfl_xor_sync(0xffffffffu, v, o);
    if ((t & 31) == 0) red[t >> 5] = v;
    __syncthreads();
    if (t < 32) {
        float s = (t < 16) ? red[t] : 0.f;
        #pragma unroll
        for (int o = 8; o > 0; o >>= 1) s += __shfl_xor_sync(0xffffffffu, s, o);
        if (t == 0) red[16] = s;
    }
    __syncthreads();
    return red[16];
}
__device__ __forceinline__ float reduce_max(float* red, int t, float v) {
    #pragma unroll
    for (int o = 16; o > 0; o >>= 1) v = fmaxf(v, __shfl_xor_sync(0xffffffffu, v, o));
    if ((t & 31) == 0) red[t >> 5] = v;
    __syncthreads();
    if (t < 32) {
        float s = (t < 16) ? red[t] : -INFINITY;
        #pragma unroll
        for (int o = 8; o > 0; o >>= 1) s = fmaxf(s, __shfl_xor_sync(0xffffffffu, s, o));
        if (t == 0) red[16] = s;
    }
    __syncthreads();
    return red[16];
}
__device__ __forceinline__ float reduce_min(float* red, int t, float v) {
    #pragma unroll
    for (int o = 16; o > 0; o >>= 1) v = fminf(v, __shfl_xor_sync(0xffffffffu, v, o));
    if ((t & 31) == 0) red[t >> 5] = v;
    __syncthreads();
    if (t < 32) {
        float s = (t < 16) ? red[t] : INFINITY;
        #pragma unroll
        for (int o = 8; o > 0; o >>= 1) s = fminf(s, __shfl_xor_sync(0xffffffffu, s, o));
        if (t == 0) red[16] = s;
    }
    __syncthreads();
    return red[16];
}

// rows direction: thread (i, quarter h) computes sum_j Areg[j] * vec[h*64+j]
__device__ __forceinline__ float mv_rows_reg(const float* __restrict__ Areg,
                                             const float* __restrict__ vec,
                                             int h) {
    const float4* v4 = reinterpret_cast<const float4*>(vec + h * QC);
    float a0 = 0.f, a1 = 0.f, a2 = 0.f, a3 = 0.f;
    #pragma unroll
    for (int k = 0; k < QC / 4; k++) {
        float4 vv = v4[k];
        a0 = fmaf(Areg[4 * k + 0], vv.x, a0);
        a1 = fmaf(Areg[4 * k + 1], vv.y, a1);
        a2 = fmaf(Areg[4 * k + 2], vv.z, a2);
        a3 = fmaf(Areg[4 * k + 3], vv.w, a3);
    }
    return (a0 + a1) + (a2 + a3);
}

// cols direction: thread (col j, row-half g) computes sum over 64 own rows.
// LDS.128 conflict-free with STRIDE=132.
__device__ __forceinline__ float mv_cols4(const float* __restrict__ A,
                                          const float* __restrict__ u,
                                          int j, int g) {
    const float4* Ac = reinterpret_cast<const float4*>(A + j * STRIDE + g * 64);
    const float4* u4 = reinterpret_cast<const float4*>(u + g * 64);
    float a0 = 0.f, a1 = 0.f, a2 = 0.f, a3 = 0.f;
    #pragma unroll
    for (int k = 0; k < 16; k++) {
        float4 aa = Ac[k];
        float4 uu = u4[k];
        a0 = fmaf(aa.x, uu.x, a0);
        a1 = fmaf(aa.y, uu.y, a1);
        a2 = fmaf(aa.z, uu.z, a2);
        a3 = fmaf(aa.w, uu.w, a3);
    }
    return (a0 + a1) + (a2 + a3);
}

__global__ void __cluster_dims__(2, 1, 1) __launch_bounds__(NTH, 1)
proj_kernel(const float* __restrict__ x_g, const float* __restrict__ A_g,
            const float* __restrict__ b_g, float* __restrict__ out_g)
{
    extern __shared__ __align__(16) unsigned char smem_raw[];
    Smem& sm = *reinterpret_cast<Smem*>(smem_raw);

    const int t    = threadIdx.x;
    const int rank = blockIdx.x & 1;
    const int prob = blockIdx.x >> 1;
    const int i_   = t & (HR - 1);
    const int h_   = t >> 7;          // column quarter (rows dir)
    const int j_   = t & (Nn - 1);
    const int g_   = t >> 8;          // row half (cols dir)

    const uint32_t peer     = rank ^ 1;
    const uint32_t gbuf_rem = mapa_rank(smem_addr(&sm.gbuf[0][0][0]), peer);
    const uint32_t sbuf_rem = mapa_rank(smem_addr(&sm.sbuf[0][0]), peer);
    int phase = 0;

    // ---- setup: load + row-normalize own half of A into SMEM; b_w; x; v0 ----
    {
        const int wid = t >> 5, lane = t & 31;
        const float* Ap = A_g + (size_t)prob * (Mm * Nn) + (size_t)rank * HR * Nn;
        for (int i = wid; i < HR; i += NTH / 32) {
            const float* arow = Ap + (size_t)i * Nn;
            float av[8];
            float ss = 0.f;
            #pragma unroll
            for (int k = 0; k < 8; k++) {
                float a = arow[lane + 32 * k];
                av[k] = a;
                ss = fmaf(a, a, ss);
            }
            #pragma unroll
            for (int o = 16; o > 0; o >>= 1) ss += __shfl_xor_sync(0xffffffffu, ss, o);
            float rn = fmaxf(sqrtf(ss), 1e-12f);
            #pragma unroll
            for (int k = 0; k < 8; k++)
                sm.A[(lane + 32 * k) * STRIDE + i] = av[k] / rn;
            if (lane == 0)
                sm.bw[i] = b_g[(size_t)prob * Mm + rank * HR + i] / rn;
        }
        if (t < Nn) {
            float xv = x_g[(size_t)prob * Nn + t];
            sm.x[t]  = xv;
            sm.x0[t] = xv;
            sm.d[t]  = 0.0625f;   // v0 = ones/||ones||
        }
    }
    __syncthreads();

    // ---- register-cache this thread's row segment: A_w[i_][h_*64 + j] ----
    float Areg[QC];
    #pragma unroll
    for (int j = 0; j < QC; j++)
        Areg[j] = sm.A[(h_ * QC + j) * STRIDE + i_];

    // ---- power iteration: v <- normalize(A^T A v), 5 iters ----
    for (int it = 0; it < PITERS; it++) {
        float p = mv_rows_reg(Areg, sm.d, h_);
        sm.part[h_][i_] = p;
        __syncthreads();
        if (t < HR)
            sm.u[t] = (sm.part[0][t] + sm.part[1][t]) + (sm.part[2][t] + sm.part[3][t]);
        __syncthreads();
        float q = mv_cols4(sm.A, sm.u, j_, g_);
        sm.gpart[g_][j_] = q;
        __syncthreads();
        int slot = phase & 1;
        if (t < Nn) {
            float qq = sm.gpart[0][t] + sm.gpart[1][t];
            sm.gbuf[slot][rank][t] = qq;
            st_remote_f32(gbuf_rem + (uint32_t)(((slot * 2 + rank) * Nn + t) * 4), qq);
        }
        cluster_sync(); phase++;
        float w = (t < Nn) ? (sm.gbuf[slot][0][t] + sm.gbuf[slot][1][t]) : 0.f;
        float s = reduce_sum(sm.red, t, w * w);
        float nv = sqrtf(s) + 1e-12f;
        if (t < Nn) sm.d[t] = w / nv;
        __syncthreads();
    }

    // ---- eta = 1 / (||A v||^2 + rho) ----
    float eta;
    {
        float p = mv_rows_reg(Areg, sm.d, h_);
        sm.part[h_][i_] = p;
        __syncthreads();
        float uv = 0.f;
        if (t < HR) {
            uv = (sm.part[0][t] + sm.part[1][t]) + (sm.part[2][t] + sm.part[3][t]);
            sm.u[t] = uv;
        }
        float sown = reduce_sum(sm.red, t, uv * uv);
        int slot = phase & 1;
        if (t == 0) {
            sm.sbuf[slot][rank] = sown;
            st_remote_f32(sbuf_rem + (uint32_t)((slot * 2 + rank) * 4), sown);
        }
        cluster_sync(); phase++;
        eta = 1.0f / ((sm.sbuf[slot][0] + sm.sbuf[slot][1]) + RHO_C);
    }

    // ---- K-step UVP on tightened constraints ----
    for (int it = 0; it < KITERS; it++) {
        float p = mv_rows_reg(Areg, sm.x, h_);
        sm.part[h_][i_] = p;
        __syncthreads();
        if (t < HR) {
            float r = (sm.part[0][t] + sm.part[1][t]) + (sm.part[2][t] + sm.part[3][t])
                      - (sm.bw[t] - MU_IN);
            sm.u[t] = fmaxf(r, 0.f);
        }
        __syncthreads();
        float q = mv_cols4(sm.A, sm.u, j_, g_);
        sm.gpart[g_][j_] = q;
        __syncthreads();
        int slot = phase & 1;
        if (t < Nn) {
            float qq = sm.gpart[0][t] + sm.gpart[1][t];
            sm.gbuf[slot][rank][t] = qq;
            st_remote_f32(gbuf_rem + (uint32_t)(((slot * 2 + rank) * Nn + t) * 4), qq);
        }
        cluster_sync(); phase++;
        if (t < Nn)
            sm.x[t] = sm.x[t] - eta * (sm.gbuf[slot][0][t] + sm.gbuf[slot][1][t]);
        __syncthreads();
    }

    // ---- stage 2: feasibility gate + alpha line search ----
    {
        float p = mv_rows_reg(Areg, sm.x, h_);
        sm.part[h_][i_] = p;
        __syncthreads();
        if (t < HR)
            sm.u[t] = (sm.part[0][t] + sm.part[1][t]) + (sm.part[2][t] + sm.part[3][t]); // Ax
        __syncthreads();
    }
    float viol = (t < HR) ? fmaxf(sm.u[t] - sm.bw[t], 0.f) : 0.f;
    float mvown = reduce_max(sm.red, t, viol);
    float maxviol;
    {
        int slot = phase & 1;
        if (t == 0) {
            sm.sbuf[slot][rank] = mvown;
            st_remote_f32(sbuf_rem + (uint32_t)((slot * 2 + rank) * 4), mvown);
        }
        cluster_sync(); phase++;
        maxviol = fmaxf(sm.sbuf[slot][0], sm.sbuf[slot][1]);
    }
    const bool do_alpha = (maxviol <= FEAS_TOL);

    if (t < Nn) sm.d[t] = sm.x0[t] - sm.x[t];
    __syncthreads();
    {
        float p = mv_rows_reg(Areg, sm.d, h_);
        sm.part[h_][i_] = p;
        __syncthreads();
    }
    float aown = INFINITY;
    if (t < HR) {
        float ad    = (sm.part[0][t] + sm.part[1][t]) + (sm.part[2][t] + sm.part[3][t]);
        float slack = sm.bw[t] - sm.u[t];
        aown = (ad > 0.f) ? slack / (ad + 1e-12f) : INFINITY;
    }
    float amin = reduce_min(sm.red, t, aown);
    float alpha;
    {
        int slot = phase & 1;
        if (t == 0) {
            sm.sbuf[slot][rank] = amin;
            st_remote_f32(sbuf_rem + (uint32_t)((slot * 2 + rank) * 4), amin);
        }
        cluster_sync(); phase++;
        alpha = fminf(sm.sbuf[slot][0], sm.sbuf[slot][1]);
    }
    if (!isfinite(alpha)) alpha = 1.0f;
    alpha = fminf(fmaxf(alpha - EPS_IN, 0.f), 1.f);

    if (rank == 0 && t < Nn) {
        float o = do_alpha ? (sm.x[t] + alpha * sm.d[t]) : sm.x[t];
        out_g[(size_t)prob * Nn + t] = o;
    }
}

extern "C" void kernel_launch(void* const* d_in, const int* in_sizes, int n_in,
                              void* d_out, int out_size) {
    const float* x = (const float*)d_in[0];
    const float* A = (const float*)d_in[1];
    const float* b = (const float*)d_in[2];
    float* out = (float*)d_out;

    const int nprob = in_sizes[0] / Nn;   // B*S
    cudaFuncSetAttribute(proj_kernel, cudaFuncAttributeMaxDynamicSharedMemorySize,
                         (int)sizeof(Smem));
    proj_kernel<<<nprob * 2, NTH, sizeof(Smem)>>>(x, A, b, out);
}

// round 3
// speedup vs baseline: 1.7610x; 1.2774x over previous
#include <cuda_runtime.h>
#include <math.h>
#include <stdint.h>

// ---------------------------------------------------------------------------
// InnerConvexViolationProjection — GB300 sm_103a, round 3
// 2-CTA cluster per problem, 512 threads/CTA. Whole A half lives in REGISTERS
// as 8x8 per-thread tiles packed f32x2 (row pairs): both matvec directions
// from registers, fma.rn.f32x2 math, SMEM only for vectors + reductions.
// Cross-CTA partial-g exchange via DSMEM stores + mbarrier (release/acquire,
// cluster scope), double-buffered, no barrier.cluster in the loop.
// ---------------------------------------------------------------------------

#define Mm       256
#define Nn       256
#define HR       128
#define NTH      512
#define KITERS   30
#define PITERS   5

#define MU_IN    1e-3f
#define RHO_C    1e-12f
#define FEAS_TOL 1e-7f
#define EPS_IN   1e-6f

typedef unsigned long long ull;

struct __align__(16) Smem {
    ull   gbar;                 // mbarrier: g-vector exchange (count 64)
    ull   sbar;                 // mbarrier: scalar exchange   (count 1)
    float part[32][132];        // r-direction partials [lane][row]
    float gpart[16][258];       // g-direction partials [tile-row][col]
    float x[Nn];
    float x0[Nn];
    float d[Nn];
    float u[HR];                // own-row vector (Av / relu(r) / Ax)
    float bw[HR];
    float gown[Nn];             // own g partial (for f4 export)
    float gbuf[2][Nn];          // peer g partial, double buffered
    float speer[2];             // peer scalar, double buffered
    float red[32];              // reduction scratch
};

// ---- packed f32x2 helpers ----
__device__ __forceinline__ ull pk2(float lo, float hi) {
    ull r; asm("mov.b64 %0, {%1, %2};" : "=l"(r) : "f"(lo), "f"(hi)); return r;
}
__device__ __forceinline__ void unpk2(ull v, float& lo, float& hi) {
    asm("mov.b64 {%0, %1}, %2;" : "=f"(lo), "=f"(hi) : "l"(v));
}
__device__ __forceinline__ void fma2(ull& d, ull a, ull b) {
    asm("fma.rn.f32x2 %0, %1, %2, %3;" : "=l"(d) : "l"(a), "l"(b), "l"(d));
}

// ---- cluster / mbarrier helpers ----
__device__ __forceinline__ uint32_t smem_u32(const void* p) {
    return (uint32_t)__cvta_generic_to_shared(const_cast<void*>(p));
}
__device__ __forceinline__ uint32_t mapa_rank(uint32_t a, uint32_t rank) {
    uint32_t r;
    asm("mapa.shared::cluster.u32 %0, %1, %2;" : "=r"(r) : "r"(a), "r"(rank));
    return r;
}
__device__ __forceinline__ void st_remote_f32(uint32_t a, float v) {
    asm volatile("st.shared::cluster.f32 [%0], %1;" :: "r"(a), "f"(v) : "memory");
}
__device__ __forceinline__ void mbar_init(uint32_t a, uint32_t cnt) {
    asm volatile("mbarrier.init.shared.b64 [%0], %1;" :: "r"(a), "r"(cnt) : "memory");
}
__device__ __forceinline__ void mbar_arrive_remote(uint32_t a) {
    asm volatile("mbarrier.arrive.release.cluster.shared::cluster.b64 _, [%0];"
                 :: "r"(a) : "memory");
}
__device__ __forceinline__ void mbar_wait(uint32_t a, uint32_t parity) {
    asm volatile(
        "{\n\t.reg .pred P;\n\t"
        "WL_%=:\n\t"
        "mbarrier.try_wait.parity.acquire.cluster.shared::cta.b64 P, [%0], %1;\n\t"
        "@P bra.uni WD_%=;\n\t"
        "bra.uni WL_%=;\n\t"
        "WD_%=:\n\t}"
        :: "r"(a), "r"(parity) : "memory");
}
__device__ __forceinline__ void cluster_sync() {
    asm volatile("barrier.cluster.arrive.aligned;" ::: "memory");
    asm volatile("barrier.cluster.wait.aligned;"   ::: "memory");
}

// ---- shuffle+SMEM block reductions over 512 threads ----
__device__ __forceinline__ float reduce_sum(float* red, int t, float v) {
    #pragma unroll
    for (int o = 16; o > 0; o >>= 1) v += __shfl_xor_sync(0xffffffffu, v, o);
    if ((t & 31) == 0) red[t >> 5] = v;
    __syncthreads();
    if (t < 32) {
        float s = (t < 16) ? red[t] : 0.f;
        #pragma unroll
        for (int o = 8; o > 0; o >>= 1) s += __shfl_xor_sync(0xffffffffu, s, o);
        if (t == 0) red[16] = s;
    }
    __syncthreads();
    return red[16];
}
__device__ __forceinline__ float reduce_max(float* red, int t, float v) {
    #pragma unroll
    for (int o = 16; o > 0; o >>= 1) v = fmaxf(v, __shfl_xor_sync(0xffffffffu, v, o));
    if ((t & 31) == 0) red[t >> 5] = v;
    __syncthreads();
    if (t < 32) {
        float s = (t < 16) ? red[t] : -INFINITY;
        #pragma unroll
        for (int o = 8; o > 0; o >>= 1) s = fmaxf(s, __shfl_xor_sync(0xffffffffu, s, o));
        if (t == 0) red[16] = s;
    }
    __syncthreads();
    return red[16];
}
__device__ __forceinline__ float reduce_min(float* red, int t, float v) {
    #pragma unroll
    for (int o = 16; o > 0; o >>= 1) v = fminf(v, __shfl_xor_sync(0xffffffffu, v, o));
    if ((t & 31) == 0) red[t >> 5] = v;
    __syncthreads();
    if (t < 32) {
        float s = (t < 16) ? red[t] : INFINITY;
        #pragma unroll
        for (int o = 8; o > 0; o >>= 1) s = fminf(s, __shfl_xor_sync(0xffffffffu, s, o));
        if (t == 0) red[16] = s;
    }
    __syncthreads();
    return red[16];
}

// r-direction: thread tile dot over its 8 cols, 4 row-pairs. Writes part[lane][8w..].
__device__ __forceinline__ void rphase(const ull Apk[8][4], Smem& sm,
                                       const float* __restrict__ vec,
                                       int lane, int w) {
    ull r2[4] = {0ull, 0ull, 0ull, 0ull};
    #pragma unroll
    for (int k = 0; k < 8; k++) {
        float xv = vec[lane + 32 * k];
        ull xx = pk2(xv, xv);
        #pragma unroll
        for (int ip = 0; ip < 4; ip++) fma2(r2[ip], Apk[k][ip], xx);
    }
    float f0, f1, f2, f3;
    unpk2(r2[0], f0, f1); unpk2(r2[1], f2, f3);
    *reinterpret_cast<float4*>(&sm.part[lane][w * 8 + 0]) = make_float4(f0, f1, f2, f3);
    unpk2(r2[2], f0, f1); unpk2(r2[3], f2, f3);
    *reinterpret_cast<float4*>(&sm.part[lane][w * 8 + 4]) = make_float4(f0, f1, f2, f3);
}

// finalize r for own row t (<128): sum 32 lane partials
__device__ __forceinline__ float rfinal(Smem& sm, int t) {
    float a0 = 0.f, a1 = 0.f, a2 = 0.f, a3 = 0.f;
    #pragma unroll
    for (int c = 0; c < 32; c += 4) {
        a0 += sm.part[c + 0][t];
        a1 += sm.part[c + 1][t];
        a2 += sm.part[c + 2][t];
        a3 += sm.part[c + 3][t];
    }
    return (a0 + a1) + (a2 + a3);
}

// g-direction: per-col dot over the thread's 8 own rows -> gpart[w][col]
__device__ __forceinline__ void gphase(const ull Apk[8][4], Smem& sm,
                                       int lane, int w) {
    ull u2[4];
    #pragma unroll
    for (int ip = 0; ip < 4; ip++)
        u2[ip] = *reinterpret_cast<const ull*>(&sm.u[w * 8 + 2 * ip]);
    #pragma unroll
    for (int k = 0; k < 8; k++) {
        ull acc = 0ull;
        #pragma unroll
        for (int ip = 0; ip < 4; ip++) fma2(acc, Apk[k][ip], u2[ip]);
        float lo, hi; unpk2(acc, lo, hi);
        sm.gpart[w][lane + 32 * k] = lo + hi;
    }
}

// stage2: own g partial for col j (sum 16 tile-rows)
__device__ __forceinline__ float gstage2(Smem& sm, int j) {
    float a0 = 0.f, a1 = 0.f;
    #pragma unroll
    for (int w2 = 0; w2 < 16; w2 += 2) {
        a0 += sm.gpart[w2 + 0][j];
        a1 += sm.gpart[w2 + 1][j];
    }
    return a0 + a1;
}

__global__ void __cluster_dims__(2, 1, 1) __launch_bounds__(NTH, 1)
proj_kernel(const float* __restrict__ x_g, const float* __restrict__ A_g,
            const float* __restrict__ b_g, float* __restrict__ out_g)
{
    extern __shared__ __align__(16) unsigned char smem_raw[];
    Smem& sm = *reinterpret_cast<Smem*>(smem_raw);

    const int t    = threadIdx.x;
    const int lane = t & 31;
    const int w    = t >> 5;            // tile-row: rows [8w, 8w+8)
    const int rank = blockIdx.x & 1;
    const int prob = blockIdx.x >> 1;

    const uint32_t peer      = rank ^ 1;
    const uint32_t gbar_loc  = smem_u32(&sm.gbar);
    const uint32_t sbar_loc  = smem_u32(&sm.sbar);
    const uint32_t gbar_rem  = mapa_rank(gbar_loc, peer);
    const uint32_t sbar_rem  = mapa_rank(sbar_loc, peer);
    const uint32_t gbuf_rem  = mapa_rank(smem_u32(&sm.gbuf[0][0]), peer);
    const uint32_t speer_rem = mapa_rank(smem_u32(&sm.speer[0]), peer);

    if (t == 0) { mbar_init(gbar_loc, 64); mbar_init(sbar_loc, 1); }
    if (t < Nn) {
        float xv = x_g[(size_t)prob * Nn + t];
        sm.x[t] = xv; sm.x0[t] = xv; sm.d[t] = 0.0625f;
    }
    __syncthreads();
    cluster_sync();   // mbarrier init visible cluster-wide before any remote arrive

    // ---- load + row-normalize own 8x8 tile straight from GMEM ----
    ull Apk[8][4];
    {
        const float* Ap = A_g + (size_t)prob * (Mm * Nn)
                        + ((size_t)(rank * HR + w * 8)) * Nn + lane;
        #pragma unroll
        for (int ip = 0; ip < 4; ip++) {
            float a0[8], a1[8];
            float s0 = 0.f, s1 = 0.f;
            #pragma unroll
            for (int k = 0; k < 8; k++) {
                a0[k] = Ap[(size_t)(2 * ip) * Nn + 32 * k];
                a1[k] = Ap[(size_t)(2 * ip + 1) * Nn + 32 * k];
                s0 = fmaf(a0[k], a0[k], s0);
                s1 = fmaf(a1[k], a1[k], s1);
            }
            #pragma unroll
            for (int o = 16; o > 0; o >>= 1) {
                s0 += __shfl_xor_sync(0xffffffffu, s0, o);
                s1 += __shfl_xor_sync(0xffffffffu, s1, o);
            }
            float rn0 = fmaxf(sqrtf(s0), 1e-12f);
            float rn1 = fmaxf(sqrtf(s1), 1e-12f);
            #pragma unroll
            for (int k = 0; k < 8; k++)
                Apk[k][ip] = pk2(a0[k] / rn0, a1[k] / rn1);
            if (lane == 0) {
                int i0 = w * 8 + 2 * ip;
                sm.bw[i0 + 0] = b_g[(size_t)prob * Mm + rank * HR + i0 + 0] / rn0;
                sm.bw[i0 + 1] = b_g[(size_t)prob * Mm + rank * HR + i0 + 1] / rn1;
            }
        }
    }
    __syncthreads();

    int ground = 0;   // g-exchange round
    int sround = 0;   // scalar-exchange round

    // ================= power iteration =================
    for (int it = 0; it < PITERS; it++) {
        rphase(Apk, sm, sm.d, lane, w);
        __syncthreads();
        if (t < HR) sm.u[t] = rfinal(sm, t);
        __syncthreads();
        gphase(Apk, sm, lane, w);
        __syncthreads();
        float gj = 0.f;
        if (t < Nn) { gj = gstage2(sm, t); sm.gown[t] = gj; }
        __syncthreads();
        int slot = ground & 1;
        if (t < 64) {
            float4 p = *reinterpret_cast<const float4*>(&sm.gown[4 * t]);
            uint32_t dst = gbuf_rem + (uint32_t)((slot * Nn + 4 * t) * 4);
            st_remote_f32(dst + 0,  p.x);
            st_remote_f32(dst + 4,  p.y);
            st_remote_f32(dst + 8,  p.z);
            st_remote_f32(dst + 12, p.w);
            mbar_arrive_remote(gbar_rem);
        }
        float wj = 0.f;
        if (t < Nn) {
            mbar_wait(gbar_loc, (uint32_t)(ground & 1));
            wj = gj + sm.gbuf[slot][t];
        }
        ground++;
        float s = reduce_sum(sm.red, t, wj * wj);   // includes 2 barriers
        float nv = sqrtf(s) + 1e-12f;
        if (t < Nn) sm.d[t] = wj / nv;
        __syncthreads();
    }

    // ================= eta =================
    float eta;
    {
        rphase(Apk, sm, sm.d, lane, w);
        __syncthreads();
        float uv = 0.f;
        if (t < HR) uv = rfinal(sm, t);
        float sown = reduce_sum(sm.red, t, uv * uv);
        int slot = sround & 1;
        if (t == 0) {
            st_remote_f32(speer_rem + (uint32_t)(slot * 4), sown);
            mbar_arrive_remote(sbar_rem);
        }
        mbar_wait(sbar_loc, (uint32_t)(sround & 1));
        sround++;
        eta = 1.0f / ((sown + sm.speer[slot]) + RHO_C);
    }

    // ================= K-step UVP =================
    for (int it = 0; it < KITERS; it++) {
        rphase(Apk, sm, sm.x, lane, w);
        __syncthreads();
        if (t < HR) {
            float r = rfinal(sm, t) - (sm.bw[t] - MU_IN);
            sm.u[t] = fmaxf(r, 0.f);
        }
        __syncthreads();
        gphase(Apk, sm, lane, w);
        __syncthreads();
        float gj = 0.f;
        if (t < Nn) { gj = gstage2(sm, t); sm.gown[t] = gj; }
        __syncthreads();
        int slot = ground & 1;
        if (t < 64) {
            float4 p = *reinterpret_cast<const float4*>(&sm.gown[4 * t]);
            uint32_t dst = gbuf_rem + (uint32_t)((slot * Nn + 4 * t) * 4);
            st_remote_f32(dst + 0,  p.x);
            st_remote_f32(dst + 4,  p.y);
            st_remote_f32(dst + 8,  p.z);
            st_remote_f32(dst + 12, p.w);
            mbar_arrive_remote(gbar_rem);
        }
        if (t < Nn) {
            mbar_wait(gbar_loc, (uint32_t)(ground & 1));
            sm.x[t] = sm.x[t] - eta * (gj + sm.gbuf[slot][t]);
        }
        ground++;
        __syncthreads();
    }

    // ================= stage 2: gate + alpha =================
    rphase(Apk, sm, sm.x, lane, w);
    __syncthreads();
    float viol = 0.f;
    if (t < HR) {
        float ax = rfinal(sm, t);
        sm.u[t] = ax;                                 // Ax for slack
        viol = fmaxf(ax - sm.bw[t], 0.f);
    }
    float mvown = reduce_max(sm.red, t, viol);        // 2 barriers (orders sm.u too)
    float maxviol;
    {
        int slot = sround & 1;
        if (t == 0) {
            st_remote_f32(speer_rem + (uint32_t)(slot * 4), mvown);
            mbar_arrive_remote(sbar_rem);
        }
        mbar_wait(sbar_loc, (uint32_t)(sround & 1));
        sround++;
        maxviol = fmaxf(mvown, sm.speer[slot]);
    }
    const bool do_alpha = (maxviol <= FEAS_TOL);

    if (t < Nn) sm.d[t] = sm.x0[t] - sm.x[t];
    __syncthreads();
    rphase(Apk, sm, sm.d, lane, w);
    __syncthreads();
    float aown = INFINITY;
    if (t < HR) {
        float ad    = rfinal(sm, t);
        float slack = sm.bw[t] - sm.u[t];
        aown = (ad > 0.f) ? slack / (ad + 1e-12f) : INFINITY;
    }
    float amin = reduce_min(sm.red, t, aown);
    float alpha;
    {
        int slot = sround & 1;
        if (t == 0) {
            st_remote_f32(speer_rem + (uint32_t)(slot * 4), amin);
            mbar_arrive_remote(sbar_rem);
        }
        mbar_wait(sbar_loc, (uint32_t)(sround & 1));
        sround++;
        alpha = fminf(amin, sm.speer[slot]);
    }
    if (!isfinite(alpha)) alpha = 1.0f;
    alpha = fminf(fmaxf(alpha - EPS_IN, 0.f), 1.f);

    if (rank == 0 && t < Nn) {
        float o = do_alpha ? (sm.x[t] + alpha * sm.d[t]) : sm.x[t];
        out_g[(size_t)prob * Nn + t] = o;
    }

    cluster_sync();   // no CTA exits while peer traffic may be in flight
}

extern "C" void kernel_launch(void* const* d_in, const int* in_sizes, int n_in,
                              void* d_out, int out_size) {
    const float* x = (const float*)d_in[0];
    const float* A = (const float*)d_in[1];
    const float* b = (const float*)d_in[2];
    float* out = (float*)d_out;

    const int nprob = in_sizes[0] / Nn;   // B*S
    cudaFuncSetAttribute(proj_kernel, cudaFuncAttributeMaxDynamicSharedMemorySize,
                         (int)sizeof(Smem));
    proj_kernel<<<nprob * 2, NTH, sizeof(Smem)>>>(x, A, b, out);
}

// round 4
// speedup vs baseline: 1.8532x; 1.0524x over previous
#include <cuda_runtime.h>
#include <math.h>
#include <stdint.h>

// ---------------------------------------------------------------------------
// InnerConvexViolationProjection — GB300 sm_103a, round 4
// 2-CTA cluster per problem, 512 threads/CTA, A half in registers (8x8 tiles,
// f32x2-packed row pairs). NEW: the A·x row reduction is a warp-internal
// f32x2 butterfly allreduce (warp w's lanes hold ALL partials for its 8 rows),
// so u feeds A^T·u straight from registers: 2 __syncthreads + 1 mbarrier wait
// per UVP iteration (was 5 + 1). b_w / b_tight live in registers.
// ---------------------------------------------------------------------------

#define Mm       256
#define Nn       256
#define HR       128
#define NTH      512
#define KITERS   30
#define PITERS   5

#define MU_IN    1e-3f
#define RHO_C    1e-12f
#define FEAS_TOL 1e-7f
#define EPS_IN   1e-6f

typedef unsigned long long ull;

struct __align__(16) Smem {
    ull   gbar;                 // mbarrier: g exchange (count 256)
    ull   sbar;                 // mbarrier: scalar exchange (count 1)
    float gpart[16][258];       // g partials [tile-row][col]
    float x[Nn];
    float x0[Nn];
    float d[Nn];
    float gbuf[2][Nn];          // peer g partial, double buffered
    float speer[2];             // peer scalar, double buffered
    float red[32];
};

// ---- packed f32x2 helpers ----
__device__ __forceinline__ ull pk2(float lo, float hi) {
    ull r; asm("mov.b64 %0, {%1, %2};" : "=l"(r) : "f"(lo), "f"(hi)); return r;
}
__device__ __forceinline__ void unpk2(ull v, float& lo, float& hi) {
    asm("mov.b64 {%0, %1}, %2;" : "=f"(lo), "=f"(hi) : "l"(v));
}
__device__ __forceinline__ void fma2(ull& d, ull a, ull b) {
    asm("fma.rn.f32x2 %0, %1, %2, %3;" : "=l"(d) : "l"(a), "l"(b), "l"(d));
}
__device__ __forceinline__ void add2(ull& d, ull a) {
    asm("add.rn.f32x2 %0, %1, %2;" : "=l"(d) : "l"(d), "l"(a));
}

// ---- cluster / mbarrier helpers ----
__device__ __forceinline__ uint32_t smem_u32(const void* p) {
    return (uint32_t)__cvta_generic_to_shared(const_cast<void*>(p));
}
__device__ __forceinline__ uint32_t mapa_rank(uint32_t a, uint32_t rank) {
    uint32_t r;
    asm("mapa.shared::cluster.u32 %0, %1, %2;" : "=r"(r) : "r"(a), "r"(rank));
    return r;
}
__device__ __forceinline__ void st_remote_f32(uint32_t a, float v) {
    asm volatile("st.shared::cluster.f32 [%0], %1;" :: "r"(a), "f"(v) : "memory");
}
__device__ __forceinline__ void mbar_init(uint32_t a, uint32_t cnt) {
    asm volatile("mbarrier.init.shared.b64 [%0], %1;" :: "r"(a), "r"(cnt) : "memory");
}
__device__ __forceinline__ void mbar_arrive_remote(uint32_t a) {
    asm volatile("mbarrier.arrive.release.cluster.shared::cluster.b64 _, [%0];"
                 :: "r"(a) : "memory");
}
__device__ __forceinline__ void mbar_wait(uint32_t a, uint32_t parity) {
    asm volatile(
        "{\n\t.reg .pred P;\n\t"
        "WL_%=:\n\t"
        "mbarrier.try_wait.parity.acquire.cluster.shared::cta.b64 P, [%0], %1;\n\t"
        "@P bra.uni WD_%=;\n\t"
        "bra.uni WL_%=;\n\t"
        "WD_%=:\n\t}"
        :: "r"(a), "r"(parity) : "memory");
}
__device__ __forceinline__ void cluster_sync() {
    asm volatile("barrier.cluster.arrive.aligned;" ::: "memory");
    asm volatile("barrier.cluster.wait.aligned;"   ::: "memory");
}

// ---- block reductions over 512 threads ----
__device__ __forceinline__ float reduce_sum(float* red, int t, float v) {
    #pragma unroll
    for (int o = 16; o > 0; o >>= 1) v += __shfl_xor_sync(0xffffffffu, v, o);
    if ((t & 31) == 0) red[t >> 5] = v;
    __syncthreads();
    if (t < 32) {
        float s = (t < 16) ? red[t] : 0.f;
        #pragma unroll
        for (int o = 8; o > 0; o >>= 1) s += __shfl_xor_sync(0xffffffffu, s, o);
        if (t == 0) red[16] = s;
    }
    __syncthreads();
    return red[16];
}
__device__ __forceinline__ float reduce_max(float* red, int t, float v) {
    #pragma unroll
    for (int o = 16; o > 0; o >>= 1) v = fmaxf(v, __shfl_xor_sync(0xffffffffu, v, o));
    if ((t & 31) == 0) red[t >> 5] = v;
    __syncthreads();
    if (t < 32) {
        float s = (t < 16) ? red[t] : -INFINITY;
        #pragma unroll
        for (int o = 8; o > 0; o >>= 1) s = fmaxf(s, __shfl_xor_sync(0xffffffffu, s, o));
        if (t == 0) red[16] = s;
    }
    __syncthreads();
    return red[16];
}
__device__ __forceinline__ float reduce_min(float* red, int t, float v) {
    #pragma unroll
    for (int o = 16; o > 0; o >>= 1) v = fminf(v, __shfl_xor_sync(0xffffffffu, v, o));
    if ((t & 31) == 0) red[t >> 5] = v;
    __syncthreads();
    if (t < 32) {
        float s = (t < 16) ? red[t] : INFINITY;
        #pragma unroll
        for (int o = 8; o > 0; o >>= 1) s = fminf(s, __shfl_xor_sync(0xffffffffu, s, o));
        if (t == 0) red[16] = s;
    }
    __syncthreads();
    return red[16];
}

// rows direction + warp allreduce: after this, EVERY lane of warp w holds the
// full A·vec sums for rows 8w..8w+7 in r2[0..3] (packed pairs).
__device__ __forceinline__ void rphase_reduce(const ull Apk[8][4],
                                              const float* __restrict__ vec,
                                              int lane, ull r2[4]) {
    r2[0] = r2[1] = r2[2] = r2[3] = 0ull;
    #pragma unroll
    for (int k = 0; k < 8; k++) {
        float xv = vec[lane + 32 * k];
        ull xx = pk2(xv, xv);
        #pragma unroll
        for (int ip = 0; ip < 4; ip++) fma2(r2[ip], Apk[k][ip], xx);
    }
    #pragma unroll
    for (int o = 16; o > 0; o >>= 1) {
        #pragma unroll
        for (int ip = 0; ip < 4; ip++) {
            ull other = __shfl_xor_sync(0xffffffffu, r2[ip], o);
            add2(r2[ip], other);
        }
    }
}

// cols direction: per-col dot over the thread's 8 own rows -> gpart[w][col]
__device__ __forceinline__ void gphase(const ull Apk[8][4], const ull u2[4],
                                       Smem& sm, int lane, int w) {
    #pragma unroll
    for (int k = 0; k < 8; k++) {
        ull acc = 0ull;
        #pragma unroll
        for (int ip = 0; ip < 4; ip++) fma2(acc, Apk[k][ip], u2[ip]);
        float lo, hi; unpk2(acc, lo, hi);
        sm.gpart[w][lane + 32 * k] = lo + hi;
    }
}

// own-half g for col j: sum 16 tile-row partials
__device__ __forceinline__ float gsum16(Smem& sm, int j) {
    float a0 = 0.f, a1 = 0.f, a2 = 0.f, a3 = 0.f;
    #pragma unroll
    for (int w2 = 0; w2 < 16; w2 += 4) {
        a0 += sm.gpart[w2 + 0][j];
        a1 += sm.gpart[w2 + 1][j];
        a2 += sm.gpart[w2 + 2][j];
        a3 += sm.gpart[w2 + 3][j];
    }
    return (a0 + a1) + (a2 + a3);
}

__global__ void __cluster_dims__(2, 1, 1) __launch_bounds__(NTH, 1)
proj_kernel(const float* __restrict__ x_g, const float* __restrict__ A_g,
            const float* __restrict__ b_g, float* __restrict__ out_g)
{
    extern __shared__ __align__(16) unsigned char smem_raw[];
    Smem& sm = *reinterpret_cast<Smem*>(smem_raw);

    const int t    = threadIdx.x;
    const int lane = t & 31;
    const int w    = t >> 5;            // tile-row: rows [8w, 8w+8)
    const int rank = blockIdx.x & 1;
    const int prob = blockIdx.x >> 1;

    const uint32_t peer      = rank ^ 1;
    const uint32_t gbar_loc  = smem_u32(&sm.gbar);
    const uint32_t sbar_loc  = smem_u32(&sm.sbar);
    const uint32_t gbar_rem  = mapa_rank(gbar_loc, peer);
    const uint32_t sbar_rem  = mapa_rank(sbar_loc, peer);
    const uint32_t gbuf_rem  = mapa_rank(smem_u32(&sm.gbuf[0][0]), peer);
    const uint32_t speer_rem = mapa_rank(smem_u32(&sm.speer[0]), peer);

    if (t == 0) { mbar_init(gbar_loc, 256); mbar_init(sbar_loc, 1); }
    if (t < Nn) {
        float xv = x_g[(size_t)prob * Nn + t];
        sm.x[t] = xv; sm.x0[t] = xv; sm.d[t] = 0.0625f;
    }
    __syncthreads();
    cluster_sync();   // mbarrier init visible cluster-wide

    // ---- load + row-normalize own 8x8 tile from GMEM; bw in registers ----
    ull Apk[8][4];
    float bw8[8];
    {
        const float* Ap = A_g + (size_t)prob * (Mm * Nn)
                        + ((size_t)(rank * HR + w * 8)) * Nn + lane;
        const float* Bp = b_g + (size_t)prob * Mm + rank * HR + w * 8;
        #pragma unroll
        for (int ip = 0; ip < 4; ip++) {
            float a0[8], a1[8];
            float s0 = 0.f, s1 = 0.f;
            #pragma unroll
            for (int k = 0; k < 8; k++) {
                a0[k] = Ap[(size_t)(2 * ip) * Nn + 32 * k];
                a1[k] = Ap[(size_t)(2 * ip + 1) * Nn + 32 * k];
                s0 = fmaf(a0[k], a0[k], s0);
                s1 = fmaf(a1[k], a1[k], s1);
            }
            #pragma unroll
            for (int o = 16; o > 0; o >>= 1) {
                s0 += __shfl_xor_sync(0xffffffffu, s0, o);
                s1 += __shfl_xor_sync(0xffffffffu, s1, o);
            }
            float rn0 = fmaxf(sqrtf(s0), 1e-12f);
            float rn1 = fmaxf(sqrtf(s1), 1e-12f);
            #pragma unroll
            for (int k = 0; k < 8; k++)
                Apk[k][ip] = pk2(a0[k] / rn0, a1[k] / rn1);
            bw8[2 * ip + 0] = Bp[2 * ip + 0] / rn0;   // broadcast LDG
            bw8[2 * ip + 1] = Bp[2 * ip + 1] / rn1;
        }
    }
    float bt8[8];
    #pragma unroll
    for (int p = 0; p < 8; p++) bt8[p] = bw8[p] - MU_IN;
    __syncthreads();

    int ground = 0;
    int sround = 0;
    ull r2[4];

    // ================= power iteration =================
    for (int it = 0; it < PITERS; it++) {
        rphase_reduce(Apk, sm.d, lane, r2);
        gphase(Apk, r2, sm, lane, w);     // u = Av directly
        __syncthreads();
        int slot = ground & 1;
        float wj = 0.f;
        if (t < Nn) {
            float gj = gsum16(sm, t);
            st_remote_f32(gbuf_rem + (uint32_t)((slot * Nn + t) * 4), gj);
            mbar_arrive_remote(gbar_rem);
            mbar_wait(gbar_loc, (uint32_t)(ground & 1));
            wj = gj + sm.gbuf[slot][t];
        }
        ground++;
        float s = reduce_sum(sm.red, t, wj * wj);
        if (t < Nn) sm.d[t] = wj / (sqrtf(s) + 1e-12f);
        __syncthreads();
    }

    // ================= eta =================
    float eta;
    {
        rphase_reduce(Apk, sm.d, lane, r2);
        float lo, hi, ss = 0.f;
        #pragma unroll
        for (int ip = 0; ip < 4; ip++) {
            unpk2(r2[ip], lo, hi);
            ss = fmaf(lo, lo, ss);
            ss = fmaf(hi, hi, ss);
        }
        float sown = reduce_sum(sm.red, t, (lane == 0) ? ss : 0.f);
        int slot = sround & 1;
        if (t == 0) {
            st_remote_f32(speer_rem + (uint32_t)(slot * 4), sown);
            mbar_arrive_remote(sbar_rem);
        }
        mbar_wait(sbar_loc, (uint32_t)(sround & 1));
        sround++;
        eta = 1.0f / ((sown + sm.speer[slot]) + RHO_C);
    }

    // ================= K-step UVP =================
    for (int it = 0; it < KITERS; it++) {
        rphase_reduce(Apk, sm.x, lane, r2);
        ull u2[4];
        #pragma unroll
        for (int ip = 0; ip < 4; ip++) {
            float lo, hi; unpk2(r2[ip], lo, hi);
            lo = fmaxf(lo - bt8[2 * ip + 0], 0.f);
            hi = fmaxf(hi - bt8[2 * ip + 1], 0.f);
            u2[ip] = pk2(lo, hi);
        }
        gphase(Apk, u2, sm, lane, w);
        __syncthreads();
        int slot = ground & 1;
        if (t < Nn) {
            float gj = gsum16(sm, t);
            st_remote_f32(gbuf_rem + (uint32_t)((slot * Nn + t) * 4), gj);
            mbar_arrive_remote(gbar_rem);
            mbar_wait(gbar_loc, (uint32_t)(ground & 1));
            sm.x[t] = sm.x[t] - eta * (gj + sm.gbuf[slot][t]);
        }
        ground++;
        __syncthreads();
    }

    // ================= stage 2: gate + alpha =================
    rphase_reduce(Apk, sm.x, lane, r2);
    float ax[8];
    unpk2(r2[0], ax[0], ax[1]); unpk2(r2[1], ax[2], ax[3]);
    unpk2(r2[2], ax[4], ax[5]); unpk2(r2[3], ax[6], ax[7]);
    float vm = 0.f;
    #pragma unroll
    for (int p = 0; p < 8; p++) vm = fmaxf(vm, ax[p] - bw8[p]);
    vm = fmaxf(vm, 0.f);
    float mvown = reduce_max(sm.red, t, vm);    // idempotent across dup lanes
    float maxviol;
    {
        int slot = sround & 1;
        if (t == 0) {
            st_remote_f32(speer_rem + (uint32_t)(slot * 4), mvown);
            mbar_arrive_remote(sbar_rem);
        }
        mbar_wait(sbar_loc, (uint32_t)(sround & 1));
        sround++;
        maxviol = fmaxf(mvown, sm.speer[slot]);
    }
    const bool do_alpha = (maxviol <= FEAS_TOL);

    if (t < Nn) sm.d[t] = sm.x0[t] - sm.x[t];
    __syncthreads();
    rphase_reduce(Apk, sm.d, lane, r2);
    float aown = INFINITY;
    #pragma unroll
    for (int ip = 0; ip < 4; ip++) {
        float adl, adh; unpk2(r2[ip], adl, adh);
        float sl = bw8[2 * ip + 0] - ax[2 * ip + 0];
        float sh = bw8[2 * ip + 1] - ax[2 * ip + 1];
        if (adl > 0.f) aown = fminf(aown, sl / (adl + 1e-12f));
        if (adh > 0.f) aown = fminf(aown, sh / (adh + 1e-12f));
    }
    float amin = reduce_min(sm.red, t, aown);   // idempotent across dup lanes
    float alpha;
    {
        int slot = sround & 1;
        if (t == 0) {
            st_remote_f32(speer_rem + (uint32_t)(slot * 4), amin);
            mbar_arrive_remote(sbar_rem);
        }
        mbar_wait(sbar_loc, (uint32_t)(sround & 1));
        sround++;
        alpha = fminf(amin, sm.speer[slot]);
    }
    if (!isfinite(alpha)) alpha = 1.0f;
    alpha = fminf(fmaxf(alpha - EPS_IN, 0.f), 1.f);

    if (rank == 0 && t < Nn) {
        float o = do_alpha ? (sm.x[t] + alpha * sm.d[t]) : sm.x[t];
        out_g[(size_t)prob * Nn + t] = o;
    }

    cluster_sync();   // no CTA exits while peer traffic may be in flight
}

extern "C" void kernel_launch(void* const* d_in, const int* in_sizes, int n_in,
                              void* d_out, int out_size) {
    const float* x = (const float*)d_in[0];
    const float* A = (const float*)d_in[1];
    const float* b = (const float*)d_in[2];
    float* out = (float*)d_out;

    const int nprob = in_sizes[0] / Nn;   // B*S
    cudaFuncSetAttribute(proj_kernel, cudaFuncAttributeMaxDynamicSharedMemorySize,
                         (int)sizeof(Smem));
    proj_kernel<<<nprob * 2, NTH, sizeof(Smem)>>>(x, A, b, out);
}

// round 5
// speedup vs baseline: 2.0021x; 1.0803x over previous
#include <cuda_runtime.h>
#include <math.h>
#include <stdint.h>

// ---------------------------------------------------------------------------
// InnerConvexViolationProjection — GB300 sm_103a, round 5
// 2-CTA cluster per problem, 512 threads/CTA, A half in registers (8x8 tiles,
// f32x2-packed). NEW: cross-CTA g exchange via cp.async.bulk (SMEM->DSMEM)
// with mbarrier complete_tx — 8 chunked copies + 8 expect_tx arrives per
// iteration instead of 256 scalar remote stores + 256 remote arrives.
// Ping-pong barriers + double-buffered staging make phase reuse safe.
// ---------------------------------------------------------------------------

#define Mm       256
#define Nn       256
#define HR       128
#define NTH      512
#define KITERS   30
#define PITERS   5

#define MU_IN    1e-3f
#define RHO_C    1e-12f
#define FEAS_TOL 1e-7f
#define EPS_IN   1e-6f

typedef unsigned long long ull;

struct __align__(16) Smem {
    ull   gbar[2];              // ping-pong mbarriers for g exchange (count 8)
    ull   sbar;                 // mbarrier: scalar exchange (count 1)
    float gpart[16][258];       // g partials [tile-row][col]
    float x[Nn];
    float x0[Nn];
    float d[Nn];
    __align__(16) float gown[2][Nn];   // own g partial, double buffered (bulk src)
    __align__(16) float gbuf[2][Nn];   // peer g partial, double buffered (bulk dst)
    float speer[2];             // peer scalar, double buffered
    float red[32];
};

// ---- packed f32x2 helpers ----
__device__ __forceinline__ ull pk2(float lo, float hi) {
    ull r; asm("mov.b64 %0, {%1, %2};" : "=l"(r) : "f"(lo), "f"(hi)); return r;
}
__device__ __forceinline__ void unpk2(ull v, float& lo, float& hi) {
    asm("mov.b64 {%0, %1}, %2;" : "=f"(lo), "=f"(hi) : "l"(v));
}
__device__ __forceinline__ void fma2(ull& d, ull a, ull b) {
    asm("fma.rn.f32x2 %0, %1, %2, %3;" : "=l"(d) : "l"(a), "l"(b), "l"(d));
}
__device__ __forceinline__ void add2(ull& d, ull a) {
    asm("add.rn.f32x2 %0, %1, %2;" : "=l"(d) : "l"(d), "l"(a));
}

// ---- cluster / mbarrier helpers ----
__device__ __forceinline__ uint32_t smem_u32(const void* p) {
    return (uint32_t)__cvta_generic_to_shared(const_cast<void*>(p));
}
__device__ __forceinline__ uint32_t mapa_rank(uint32_t a, uint32_t rank) {
    uint32_t r;
    asm("mapa.shared::cluster.u32 %0, %1, %2;" : "=r"(r) : "r"(a), "r"(rank));
    return r;
}
__device__ __forceinline__ void st_remote_f32(uint32_t a, float v) {
    asm volatile("st.shared::cluster.f32 [%0], %1;" :: "r"(a), "f"(v) : "memory");
}
__device__ __forceinline__ void mbar_init(uint32_t a, uint32_t cnt) {
    asm volatile("mbarrier.init.shared.b64 [%0], %1;" :: "r"(a), "r"(cnt) : "memory");
}
__device__ __forceinline__ void mbar_arrive_remote(uint32_t a) {
    asm volatile("mbarrier.arrive.release.cluster.shared::cluster.b64 _, [%0];"
                 :: "r"(a) : "memory");
}
// expect_tx + arrive on the PEER's barrier (issued by sender, program-order
// before its bulk copy => no expect/complete race)
__device__ __forceinline__ void mbar_expect_remote(uint32_t a, uint32_t bytes) {
    asm volatile("mbarrier.arrive.expect_tx.shared::cluster.b64 _, [%0], %1;"
                 :: "r"(a), "r"(bytes) : "memory");
}
// SMEM(cta) -> SMEM(peer cta) bulk copy, completion at peer's mbarrier
__device__ __forceinline__ void bulk_copy_to_peer(uint32_t dst_cluster,
                                                  uint32_t src_cta,
                                                  uint32_t bytes,
                                                  uint32_t peer_mbar) {
    asm volatile(
        "cp.async.bulk.shared::cluster.shared::cta.mbarrier::complete_tx::bytes "
        "[%0], [%1], %2, [%3];"
        :: "r"(dst_cluster), "r"(src_cta), "r"(bytes), "r"(peer_mbar) : "memory");
}
__device__ __forceinline__ void fence_proxy_async_cta() {
    asm volatile("fence.proxy.async.shared::cta;" ::: "memory");
}
__device__ __forceinline__ void mbar_wait(uint32_t a, uint32_t parity) {
    asm volatile(
        "{\n\t.reg .pred P;\n\t"
        "WL_%=:\n\t"
        "mbarrier.try_wait.parity.acquire.cluster.shared::cta.b64 P, [%0], %1, 0x989680;\n\t"
        "@P bra.uni WD_%=;\n\t"
        "bra.uni WL_%=;\n\t"
        "WD_%=:\n\t}"
        :: "r"(a), "r"(parity) : "memory");
}
__device__ __forceinline__ void cluster_sync() {
    asm volatile("barrier.cluster.arrive.aligned;" ::: "memory");
    asm volatile("barrier.cluster.wait.aligned;"   ::: "memory");
}

// ---- block reductions over 512 threads ----
__device__ __forceinline__ float reduce_sum(float* red, int t, float v) {
    #pragma unroll
    for (int o = 16; o > 0; o >>= 1) v += __shfl_xor_sync(0xffffffffu, v, o);
    if ((t & 31) == 0) red[t >> 5] = v;
    __syncthreads();
    if (t < 32) {
        float s = (t < 16) ? red[t] : 0.f;
        #pragma unroll
        for (int o = 8; o > 0; o >>= 1) s += __shfl_xor_sync(0xffffffffu, s, o);
        if (t == 0) red[16] = s;
    }
    __syncthreads();
    return red[16];
}
__device__ __forceinline__ float reduce_max(float* red, int t, float v) {
    #pragma unroll
    for (int o = 16; o > 0; o >>= 1) v = fmaxf(v, __shfl_xor_sync(0xffffffffu, v, o));
    if ((t & 31) == 0) red[t >> 5] = v;
    __syncthreads();
    if (t < 32) {
        float s = (t < 16) ? red[t] : -INFINITY;
        #pragma unroll
        for (int o = 8; o > 0; o >>= 1) s = fmaxf(s, __shfl_xor_sync(0xffffffffu, s, o));
        if (t == 0) red[16] = s;
    }
    __syncthreads();
    return red[16];
}
__device__ __forceinline__ float reduce_min(float* red, int t, float v) {
    #pragma unroll
    for (int o = 16; o > 0; o >>= 1) v = fminf(v, __shfl_xor_sync(0xffffffffu, v, o));
    if ((t & 31) == 0) red[t >> 5] = v;
    __syncthreads();
    if (t < 32) {
        float s = (t < 16) ? red[t] : INFINITY;
        #pragma unroll
        for (int o = 8; o > 0; o >>= 1) s = fminf(s, __shfl_xor_sync(0xffffffffu, s, o));
        if (t == 0) red[16] = s;
    }
    __syncthreads();
    return red[16];
}

// rows direction + warp allreduce: every lane of warp w ends with the full
// A·vec sums for rows 8w..8w+7 in r2[0..3] (packed pairs).
__device__ __forceinline__ void rphase_reduce(const ull Apk[8][4],
                                              const float* __restrict__ vec,
                                              int lane, ull r2[4]) {
    r2[0] = r2[1] = r2[2] = r2[3] = 0ull;
    #pragma unroll
    for (int k = 0; k < 8; k++) {
        float xv = vec[lane + 32 * k];
        ull xx = pk2(xv, xv);
        #pragma unroll
        for (int ip = 0; ip < 4; ip++) fma2(r2[ip], Apk[k][ip], xx);
    }
    #pragma unroll
    for (int o = 16; o > 0; o >>= 1) {
        #pragma unroll
        for (int ip = 0; ip < 4; ip++) {
            ull other = __shfl_xor_sync(0xffffffffu, r2[ip], o);
            add2(r2[ip], other);
        }
    }
}

// cols direction: per-col dot over the thread's 8 own rows -> gpart[w][col]
__device__ __forceinline__ void gphase(const ull Apk[8][4], const ull u2[4],
                                       Smem& sm, int lane, int w) {
    #pragma unroll
    for (int k = 0; k < 8; k++) {
        ull acc = 0ull;
        #pragma unroll
        for (int ip = 0; ip < 4; ip++) fma2(acc, Apk[k][ip], u2[ip]);
        float lo, hi; unpk2(acc, lo, hi);
        sm.gpart[w][lane + 32 * k] = lo + hi;
    }
}

// own-half g for col j: sum 16 tile-row partials
__device__ __forceinline__ float gsum16(Smem& sm, int j) {
    float a0 = 0.f, a1 = 0.f, a2 = 0.f, a3 = 0.f;
    #pragma unroll
    for (int w2 = 0; w2 < 16; w2 += 4) {
        a0 += sm.gpart[w2 + 0][j];
        a1 += sm.gpart[w2 + 1][j];
        a2 += sm.gpart[w2 + 2][j];
        a3 += sm.gpart[w2 + 3][j];
    }
    return (a0 + a1) + (a2 + a3);
}

// g-exchange: warps 0..7 each finish their 32-col chunk, stage it in gown,
// and lane 0 bulk-copies the 128B chunk to the peer with expect_tx+complete_tx.
// Returns this thread's own gj (threads t<256 only; others return 0).
__device__ __forceinline__ float g_exchange(Smem& sm, int t, int lane, int w,
                                            int slot,
                                            uint32_t gbar_rem_slot,
                                            uint32_t gbuf_rem_slot) {
    float gj = 0.f;
    if (t < Nn) {
        gj = gsum16(sm, t);
        sm.gown[slot][t] = gj;
        __syncwarp();
        if (lane == 0) {
            fence_proxy_async_cta();
            uint32_t off = (uint32_t)(w * 32 * 4);   // warp's 128B chunk
            mbar_expect_remote(gbar_rem_slot, 128);
            bulk_copy_to_peer(gbuf_rem_slot + off,
                              smem_u32(&sm.gown[slot][w * 32]),
                              128, gbar_rem_slot);
        }
    }
    return gj;
}

__global__ void __cluster_dims__(2, 1, 1) __launch_bounds__(NTH, 1)
proj_kernel(const float* __restrict__ x_g, const float* __restrict__ A_g,
            const float* __restrict__ b_g, float* __restrict__ out_g)
{
    extern __shared__ __align__(16) unsigned char smem_raw[];
    Smem& sm = *reinterpret_cast<Smem*>(smem_raw);

    const int t    = threadIdx.x;
    const int lane = t & 31;
    const int w    = t >> 5;            // tile-row: rows [8w, 8w+8)
    const int rank = blockIdx.x & 1;
    const int prob = blockIdx.x >> 1;

    const uint32_t peer      = rank ^ 1;
    const uint32_t gbar_loc0 = smem_u32(&sm.gbar[0]);
    const uint32_t gbar_loc1 = smem_u32(&sm.gbar[1]);
    const uint32_t sbar_loc  = smem_u32(&sm.sbar);
    const uint32_t gbar_rem0 = mapa_rank(gbar_loc0, peer);
    const uint32_t gbar_rem1 = mapa_rank(gbar_loc1, peer);
    const uint32_t sbar_rem  = mapa_rank(sbar_loc, peer);
    const uint32_t gbuf_rem0 = mapa_rank(smem_u32(&sm.gbuf[0][0]), peer);
    const uint32_t gbuf_rem1 = mapa_rank(smem_u32(&sm.gbuf[1][0]), peer);
    const uint32_t speer_rem = mapa_rank(smem_u32(&sm.speer[0]), peer);

    if (t == 0) {
        mbar_init(gbar_loc0, 8);   // 8 expect_tx arrives per phase
        mbar_init(gbar_loc1, 8);
        mbar_init(sbar_loc, 1);
    }
    if (t < Nn) {
        float xv = x_g[(size_t)prob * Nn + t];
        sm.x[t] = xv; sm.x0[t] = xv; sm.d[t] = 0.0625f;
    }
    __syncthreads();
    cluster_sync();   // mbarrier init visible cluster-wide

    // ---- load + row-normalize own 8x8 tile from GMEM; bw in registers ----
    ull Apk[8][4];
    float bw8[8];
    {
        const float* Ap = A_g + (size_t)prob * (Mm * Nn)
                        + ((size_t)(rank * HR + w * 8)) * Nn + lane;
        const float* Bp = b_g + (size_t)prob * Mm + rank * HR + w * 8;
        #pragma unroll
        for (int ip = 0; ip < 4; ip++) {
            float a0[8], a1[8];
            float s0 = 0.f, s1 = 0.f;
            #pragma unroll
            for (int k = 0; k < 8; k++) {
                a0[k] = Ap[(size_t)(2 * ip) * Nn + 32 * k];
                a1[k] = Ap[(size_t)(2 * ip + 1) * Nn + 32 * k];
                s0 = fmaf(a0[k], a0[k], s0);
                s1 = fmaf(a1[k], a1[k], s1);
            }
            #pragma unroll
            for (int o = 16; o > 0; o >>= 1) {
                s0 += __shfl_xor_sync(0xffffffffu, s0, o);
                s1 += __shfl_xor_sync(0xffffffffu, s1, o);
            }
            float rn0 = fmaxf(sqrtf(s0), 1e-12f);
            float rn1 = fmaxf(sqrtf(s1), 1e-12f);
            #pragma unroll
            for (int k = 0; k < 8; k++)
                Apk[k][ip] = pk2(a0[k] / rn0, a1[k] / rn1);
            bw8[2 * ip + 0] = Bp[2 * ip + 0] / rn0;
            bw8[2 * ip + 1] = Bp[2 * ip + 1] / rn1;
        }
    }
    float bt8[8];
    #pragma unroll
    for (int p = 0; p < 8; p++) bt8[p] = bw8[p] - MU_IN;
    __syncthreads();

    int ground = 0;   // g-exchange round: bar = ground&1, parity = (ground>>1)&1
    int sround = 0;
    ull r2[4];

    // ================= power iteration =================
    for (int it = 0; it < PITERS; it++) {
        rphase_reduce(Apk, sm.d, lane, r2);
        gphase(Apk, r2, sm, lane, w);     // u = Av directly from registers
        __syncthreads();
        int slot = ground & 1;
        float gj = g_exchange(sm, t, lane, w, slot,
                              slot ? gbar_rem1 : gbar_rem0,
                              slot ? gbuf_rem1 : gbuf_rem0);
        float wj = 0.f;
        if (t < Nn) {
            mbar_wait(slot ? gbar_loc1 : gbar_loc0, (uint32_t)((ground >> 1) & 1));
            wj = gj + sm.gbuf[slot][t];
        }
        ground++;
        float s = reduce_sum(sm.red, t, wj * wj);
        if (t < Nn) sm.d[t] = wj / (sqrtf(s) + 1e-12f);
        __syncthreads();
    }

    // ================= eta =================
    float eta;
    {
        rphase_reduce(Apk, sm.d, lane, r2);
        float lo, hi, ss = 0.f;
        #pragma unroll
        for (int ip = 0; ip < 4; ip++) {
            unpk2(r2[ip], lo, hi);
            ss = fmaf(lo, lo, ss);
            ss = fmaf(hi, hi, ss);
        }
        float sown = reduce_sum(sm.red, t, (lane == 0) ? ss : 0.f);
        int slot = sround & 1;
        if (t == 0) {
            st_remote_f32(speer_rem + (uint32_t)(slot * 4), sown);
            mbar_arrive_remote(sbar_rem);
        }
        mbar_wait(sbar_loc, (uint32_t)(sround & 1));
        sround++;
        eta = 1.0f / ((sown + sm.speer[slot]) + RHO_C);
    }

    // ================= K-step UVP =================
    for (int it = 0; it < KITERS; it++) {
        rphase_reduce(Apk, sm.x, lane, r2);
        ull u2[4];
        #pragma unroll
        for (int ip = 0; ip < 4; ip++) {
            float lo, hi; unpk2(r2[ip], lo, hi);
            lo = fmaxf(lo - bt8[2 * ip + 0], 0.f);
            hi = fmaxf(hi - bt8[2 * ip + 1], 0.f);
            u2[ip] = pk2(lo, hi);
        }
        gphase(Apk, u2, sm, lane, w);
        __syncthreads();
        int slot = ground & 1;
        float gj = g_exchange(sm, t, lane, w, slot,
                              slot ? gbar_rem1 : gbar_rem0,
                              slot ? gbuf_rem1 : gbuf_rem0);
        if (t < Nn) {
            mbar_wait(slot ? gbar_loc1 : gbar_loc0, (uint32_t)((ground >> 1) & 1));
            sm.x[t] = sm.x[t] - eta * (gj + sm.gbuf[slot][t]);
        }
        ground++;
        __syncthreads();
    }

    // ================= stage 2: gate + alpha =================
    rphase_reduce(Apk, sm.x, lane, r2);
    float ax[8];
    unpk2(r2[0], ax[0], ax[1]); unpk2(r2[1], ax[2], ax[3]);
    unpk2(r2[2], ax[4], ax[5]); unpk2(r2[3], ax[6], ax[7]);
    float vm = 0.f;
    #pragma unroll
    for (int p = 0; p < 8; p++) vm = fmaxf(vm, ax[p] - bw8[p]);
    vm = fmaxf(vm, 0.f);
    float mvown = reduce_max(sm.red, t, vm);
    float maxviol;
    {
        int slot = sround & 1;
        if (t == 0) {
            st_remote_f32(speer_rem + (uint32_t)(slot * 4), mvown);
            mbar_arrive_remote(sbar_rem);
        }
        mbar_wait(sbar_loc, (uint32_t)(sround & 1));
        sround++;
        maxviol = fmaxf(mvown, sm.speer[slot]);
    }
    const bool do_alpha = (maxviol <= FEAS_TOL);

    if (t < Nn) sm.d[t] = sm.x0[t] - sm.x[t];
    __syncthreads();
    rphase_reduce(Apk, sm.d, lane, r2);
    float aown = INFINITY;
    #pragma unroll
    for (int ip = 0; ip < 4; ip++) {
        float adl, adh; unpk2(r2[ip], adl, adh);
        float sl = bw8[2 * ip + 0] - ax[2 * ip + 0];
        float sh = bw8[2 * ip + 1] - ax[2 * ip + 1];
        if (adl > 0.f) aown = fminf(aown, sl / (adl + 1e-12f));
        if (adh > 0.f) aown = fminf(aown, sh / (adh + 1e-12f));
    }
    float amin = reduce_min(sm.red, t, aown);
    float alpha;
    {
        int slot = sround & 1;
        if (t == 0) {
            st_remote_f32(speer_rem + (uint32_t)(slot * 4), amin);
            mbar_arrive_remote(sbar_rem);
        }
        mbar_wait(sbar_loc, (uint32_t)(sround & 1));
        sround++;
        alpha = fminf(amin, sm.speer[slot]);
    }
    if (!isfinite(alpha)) alpha = 1.0f;
    alpha = fminf(fmaxf(alpha - EPS_IN, 0.f), 1.f);

    if (rank == 0 && t < Nn) {
        float o = do_alpha ? (sm.x[t] + alpha * sm.d[t]) : sm.x[t];
        out_g[(size_t)prob * Nn + t] = o;
    }

    cluster_sync();   // no CTA exits while peer traffic may be in flight
}

extern "C" void kernel_launch(void* const* d_in, const int* in_sizes, int n_in,
                              void* d_out, int out_size) {
    const float* x = (const float*)d_in[0];
    const float* A = (const float*)d_in[1];
    const float* b = (const float*)d_in[2];
    float* out = (float*)d_out;

    const int nprob = in_sizes[0] / Nn;   // B*S
    cudaFuncSetAttribute(proj_kernel, cudaFuncAttributeMaxDynamicSharedMemorySize,
                         (int)sizeof(Smem));
    proj_kernel<<<nprob * 2, NTH, sizeof(Smem)>>>(x, A, b, out);
}

// round 6
// speedup vs baseline: 2.1711x; 1.0844x over previous
#include <cuda_runtime.h>
#include <math.h>
#include <stdint.h>

// ---------------------------------------------------------------------------
// InnerConvexViolationProjection — GB300 sm_103a, round 6
// 2-CTA cluster/problem, 512 thr/CTA, A half in regs (8x8 f32x2 row pairs).
// NEW (instruction diet): row reduction = reduce-scatter (same pairing tree
// as the old butterfly, half the instructions); lane owns row (lane>>2)&7 and
// all row-wise math (relu/bt/viol/alpha) is scalar per lane. gphase stores
// packed f32x2 partials (STS.64, no hadd); gsum adds them with add2.
// Exchange: cp.async.bulk SMEM->peer SMEM + mbarrier expect/complete (R5).
// ---------------------------------------------------------------------------

#define Mm       256
#define Nn       256
#define HR       128
#define NTH      512
#define KITERS   30
#define PITERS   5

#define MU_IN    1e-3f
#define RHO_C    1e-12f
#define FEAS_TOL 1e-7f
#define EPS_IN   1e-6f

typedef unsigned long long ull;

struct __align__(16) Smem {
    ull   gbar[2];              // ping-pong mbarriers for g exchange (count 8)
    ull   sbar;                 // mbarrier: scalar exchange (count 1)
    ull   gpart2[16][258];      // packed g partials [tile-row][col] (f32x2 = row-pair contrib)
    float u8[16][8];            // per-warp row values (u) for gphase broadcast
    float x[Nn];
    float x0[Nn];
    float d[Nn];
    __align__(16) float gown[2][Nn];   // own g, double buffered (bulk src)
    __align__(16) float gbuf[2][Nn];   // peer g, double buffered (bulk dst)
    float speer[2];
    float red[32];
};

// ---- packed f32x2 helpers ----
__device__ __forceinline__ ull pk2(float lo, float hi) {
    ull r; asm("mov.b64 %0, {%1, %2};" : "=l"(r) : "f"(lo), "f"(hi)); return r;
}
__device__ __forceinline__ void unpk2(ull v, float& lo, float& hi) {
    asm("mov.b64 {%0, %1}, %2;" : "=f"(lo), "=f"(hi) : "l"(v));
}
__device__ __forceinline__ void fma2(ull& d, ull a, ull b) {
    asm("fma.rn.f32x2 %0, %1, %2, %3;" : "=l"(d) : "l"(a), "l"(b), "l"(d));
}
__device__ __forceinline__ void add2(ull& d, ull a) {
    asm("add.rn.f32x2 %0, %1, %2;" : "=l"(d) : "l"(d), "l"(a));
}

// ---- cluster / mbarrier helpers ----
__device__ __forceinline__ uint32_t smem_u32(const void* p) {
    return (uint32_t)__cvta_generic_to_shared(const_cast<void*>(p));
}
__device__ __forceinline__ uint32_t mapa_rank(uint32_t a, uint32_t rank) {
    uint32_t r;
    asm("mapa.shared::cluster.u32 %0, %1, %2;" : "=r"(r) : "r"(a), "r"(rank));
    return r;
}
__device__ __forceinline__ void st_remote_f32(uint32_t a, float v) {
    asm volatile("st.shared::cluster.f32 [%0], %1;" :: "r"(a), "f"(v) : "memory");
}
__device__ __forceinline__ void mbar_init(uint32_t a, uint32_t cnt) {
    asm volatile("mbarrier.init.shared.b64 [%0], %1;" :: "r"(a), "r"(cnt) : "memory");
}
__device__ __forceinline__ void mbar_arrive_remote(uint32_t a) {
    asm volatile("mbarrier.arrive.release.cluster.shared::cluster.b64 _, [%0];"
                 :: "r"(a) : "memory");
}
__device__ __forceinline__ void mbar_expect_remote(uint32_t a, uint32_t bytes) {
    asm volatile("mbarrier.arrive.expect_tx.shared::cluster.b64 _, [%0], %1;"
                 :: "r"(a), "r"(bytes) : "memory");
}
__device__ __forceinline__ void bulk_copy_to_peer(uint32_t dst_cluster,
                                                  uint32_t src_cta,
                                                  uint32_t bytes,
                                                  uint32_t peer_mbar) {
    asm volatile(
        "cp.async.bulk.shared::cluster.shared::cta.mbarrier::complete_tx::bytes "
        "[%0], [%1], %2, [%3];"
        :: "r"(dst_cluster), "r"(src_cta), "r"(bytes), "r"(peer_mbar) : "memory");
}
__device__ __forceinline__ void fence_proxy_async_cta() {
    asm volatile("fence.proxy.async.shared::cta;" ::: "memory");
}
__device__ __forceinline__ void mbar_wait(uint32_t a, uint32_t parity) {
    asm volatile(
        "{\n\t.reg .pred P;\n\t"
        "WL_%=:\n\t"
        "mbarrier.try_wait.parity.acquire.cluster.shared::cta.b64 P, [%0], %1, 0x989680;\n\t"
        "@P bra.uni WD_%=;\n\t"
        "bra.uni WL_%=;\n\t"
        "WD_%=:\n\t}"
        :: "r"(a), "r"(parity) : "memory");
}
__device__ __forceinline__ void cluster_sync() {
    asm volatile("barrier.cluster.arrive.aligned;" ::: "memory");
    asm volatile("barrier.cluster.wait.aligned;"   ::: "memory");
}

// ---- block reductions over 512 threads ----
__device__ __forceinline__ float reduce_sum(float* red, int t, float v) {
    #pragma unroll
    for (int o = 16; o > 0; o >>= 1) v += __shfl_xor_sync(0xffffffffu, v, o);
    if ((t & 31) == 0) red[t >> 5] = v;
    __syncthreads();
    if (t < 32) {
        float s = (t < 16) ? red[t] : 0.f;
        #pragma unroll
        for (int o = 8; o > 0; o >>= 1) s += __shfl_xor_sync(0xffffffffu, s, o);
        if (t == 0) red[16] = s;
    }
    __syncthreads();
    return red[16];
}
__device__ __forceinline__ float reduce_max(float* red, int t, float v) {
    #pragma unroll
    for (int o = 16; o > 0; o >>= 1) v = fmaxf(v, __shfl_xor_sync(0xffffffffu, v, o));
    if ((t & 31) == 0) red[t >> 5] = v;
    __syncthreads();
    if (t < 32) {
        float s = (t < 16) ? red[t] : -INFINITY;
        #pragma unroll
        for (int o = 8; o > 0; o >>= 1) s = fmaxf(s, __shfl_xor_sync(0xffffffffu, s, o));
        if (t == 0) red[16] = s;
    }
    __syncthreads();
    return red[16];
}
__device__ __forceinline__ float reduce_min(float* red, int t, float v) {
    #pragma unroll
    for (int o = 16; o > 0; o >>= 1) v = fminf(v, __shfl_xor_sync(0xffffffffu, v, o));
    if ((t & 31) == 0) red[t >> 5] = v;
    __syncthreads();
    if (t < 32) {
        float s = (t < 16) ? red[t] : INFINITY;
        #pragma unroll
        for (int o = 8; o > 0; o >>= 1) s = fminf(s, __shfl_xor_sync(0xffffffffu, s, o));
        if (t == 0) red[16] = s;
    }
    __syncthreads();
    return red[16];
}

// rows direction fma: r2[ip] = packed partial for rows (2ip, 2ip+1) over this
// lane's 8 columns {lane + 32k}.
__device__ __forceinline__ void rphase_fma(const ull Apk[8][4],
                                           const float* __restrict__ vec,
                                           int lane, ull r2[4]) {
    r2[0] = r2[1] = r2[2] = r2[3] = 0ull;
    #pragma unroll
    for (int k = 0; k < 8; k++) {
        float xv = vec[lane + 32 * k];
        ull xx = pk2(xv, xv);
        #pragma unroll
        for (int ip = 0; ip < 4; ip++) fma2(r2[ip], Apk[k][ip], xx);
    }
}

// reduce-scatter (same xor 16/8/4/2/1 pairing tree as a full butterfly =>
// bitwise-identical sums). Returns the full A·vec dot for row (lane>>2)&7;
// all 4 lanes of each group hold the same value.
__device__ __forceinline__ float rscatter(ull r2[4], int lane) {
    const bool b4 = (lane & 16) != 0;
    ull k0 = b4 ? r2[2] : r2[0];
    ull k1 = b4 ? r2[3] : r2[1];
    ull s0 = b4 ? r2[0] : r2[2];
    ull s1 = b4 ? r2[1] : r2[3];
    s0 = __shfl_xor_sync(0xffffffffu, s0, 16);
    s1 = __shfl_xor_sync(0xffffffffu, s1, 16);
    add2(k0, s0); add2(k1, s1);
    const bool b3 = (lane & 8) != 0;
    ull k = b3 ? k1 : k0;
    ull s = b3 ? k0 : k1;
    s = __shfl_xor_sync(0xffffffffu, s, 8);
    add2(k, s);
    float lo, hi; unpk2(k, lo, hi);
    const bool b2 = (lane & 4) != 0;
    float kf = b2 ? hi : lo;
    float sf = b2 ? lo : hi;
    kf += __shfl_xor_sync(0xffffffffu, sf, 4);
    kf += __shfl_xor_sync(0xffffffffu, kf, 2);
    kf += __shfl_xor_sync(0xffffffffu, kf, 1);
    return kf;
}

// broadcast the warp's 8 row values via SMEM, return packed pairs for gphase
__device__ __forceinline__ void u_broadcast(Smem& sm, int lane, int w, int rg,
                                            float val, ull u2[4]) {
    if ((lane & 3) == 0) sm.u8[w][rg] = val;
    __syncwarp();
    #pragma unroll
    for (int ip = 0; ip < 4; ip++)
        u2[ip] = *reinterpret_cast<const ull*>(&sm.u8[w][2 * ip]);
}

// cols direction: packed per-col contribution of the thread's 8 rows (as 4
// row-pairs) -> gpart2[w][col] (STS.64, no hadd here)
__device__ __forceinline__ void gphase(const ull Apk[8][4], const ull u2[4],
                                       Smem& sm, int lane, int w) {
    #pragma unroll
    for (int k = 0; k < 8; k++) {
        ull acc = 0ull;
        #pragma unroll
        for (int ip = 0; ip < 4; ip++) fma2(acc, Apk[k][ip], u2[ip]);
        sm.gpart2[w][lane + 32 * k] = acc;
    }
}

// own-half g for col j: add2 the 16 packed partials, hadd once
__device__ __forceinline__ float gsum16(Smem& sm, int j) {
    ull a0 = 0ull, a1 = 0ull, a2 = 0ull, a3 = 0ull;
    #pragma unroll
    for (int w2 = 0; w2 < 16; w2 += 4) {
        add2(a0, sm.gpart2[w2 + 0][j]);
        add2(a1, sm.gpart2[w2 + 1][j]);
        add2(a2, sm.gpart2[w2 + 2][j]);
        add2(a3, sm.gpart2[w2 + 3][j]);
    }
    add2(a0, a1); add2(a2, a3); add2(a0, a2);
    float lo, hi; unpk2(a0, lo, hi);
    return lo + hi;
}

// g exchange: warps 0..7 stage their 32-col chunk and lane 0 bulk-copies it
__device__ __forceinline__ float g_exchange(Smem& sm, int t, int lane, int w,
                                            int slot,
                                            uint32_t gbar_rem_slot,
                                            uint32_t gbuf_rem_slot) {
    float gj = 0.f;
    if (t < Nn) {
        gj = gsum16(sm, t);
        sm.gown[slot][t] = gj;
        __syncwarp();
        if (lane == 0) {
            fence_proxy_async_cta();
            uint32_t off = (uint32_t)(w * 32 * 4);
            mbar_expect_remote(gbar_rem_slot, 128);
            bulk_copy_to_peer(gbuf_rem_slot + off,
                              smem_u32(&sm.gown[slot][w * 32]),
                              128, gbar_rem_slot);
        }
    }
    return gj;
}

__global__ void __cluster_dims__(2, 1, 1) __launch_bounds__(NTH, 1)
proj_kernel(const float* __restrict__ x_g, const float* __restrict__ A_g,
            const float* __restrict__ b_g, float* __restrict__ out_g)
{
    extern __shared__ __align__(16) unsigned char smem_raw[];
    Smem& sm = *reinterpret_cast<Smem*>(smem_raw);

    const int t    = threadIdx.x;
    const int lane = t & 31;
    const int w    = t >> 5;            // tile-row: rows [8w, 8w+8)
    const int rg   = (lane >> 2) & 7;   // owned row within tile after rscatter
    const int rank = blockIdx.x & 1;
    const int prob = blockIdx.x >> 1;

    const uint32_t peer      = rank ^ 1;
    const uint32_t gbar_loc0 = smem_u32(&sm.gbar[0]);
    const uint32_t gbar_loc1 = smem_u32(&sm.gbar[1]);
    const uint32_t sbar_loc  = smem_u32(&sm.sbar);
    const uint32_t gbar_rem0 = mapa_rank(gbar_loc0, peer);
    const uint32_t gbar_rem1 = mapa_rank(gbar_loc1, peer);
    const uint32_t sbar_rem  = mapa_rank(sbar_loc, peer);
    const uint32_t gbuf_rem0 = mapa_rank(smem_u32(&sm.gbuf[0][0]), peer);
    const uint32_t gbuf_rem1 = mapa_rank(smem_u32(&sm.gbuf[1][0]), peer);
    const uint32_t speer_rem = mapa_rank(smem_u32(&sm.speer[0]), peer);

    if (t == 0) {
        mbar_init(gbar_loc0, 8);
        mbar_init(gbar_loc1, 8);
        mbar_init(sbar_loc, 1);
    }
    if (t < Nn) {
        float xv = x_g[(size_t)prob * Nn + t];
        sm.x[t] = xv; sm.x0[t] = xv; sm.d[t] = 0.0625f;
    }
    __syncthreads();
    cluster_sync();

    // ---- load + row-normalize own 8x8 tile; per-lane bw for owned row ----
    ull Apk[8][4];
    float bw_own = 0.f;
    {
        const float* Ap = A_g + (size_t)prob * (Mm * Nn)
                        + ((size_t)(rank * HR + w * 8)) * Nn + lane;
        const float* Bp = b_g + (size_t)prob * Mm + rank * HR + w * 8;
        #pragma unroll
        for (int ip = 0; ip < 4; ip++) {
            float a0[8], a1[8];
            float s0 = 0.f, s1 = 0.f;
            #pragma unroll
            for (int k = 0; k < 8; k++) {
                a0[k] = Ap[(size_t)(2 * ip) * Nn + 32 * k];
                a1[k] = Ap[(size_t)(2 * ip + 1) * Nn + 32 * k];
                s0 = fmaf(a0[k], a0[k], s0);
                s1 = fmaf(a1[k], a1[k], s1);
            }
            #pragma unroll
            for (int o = 16; o > 0; o >>= 1) {
                s0 += __shfl_xor_sync(0xffffffffu, s0, o);
                s1 += __shfl_xor_sync(0xffffffffu, s1, o);
            }
            float rn0 = fmaxf(sqrtf(s0), 1e-12f);
            float rn1 = fmaxf(sqrtf(s1), 1e-12f);
            #pragma unroll
            for (int k = 0; k < 8; k++)
                Apk[k][ip] = pk2(a0[k] / rn0, a1[k] / rn1);
            float bv0 = Bp[2 * ip + 0] / rn0;
            float bv1 = Bp[2 * ip + 1] / rn1;
            if (rg == 2 * ip)     bw_own = bv0;
            if (rg == 2 * ip + 1) bw_own = bv1;
        }
    }
    const float bt_own = bw_own - MU_IN;
    __syncthreads();

    int ground = 0;   // bar = ground&1, parity = (ground>>1)&1
    int sround = 0;
    ull r2[4], u2[4];

    // ================= power iteration =================
    for (int it = 0; it < PITERS; it++) {
        rphase_fma(Apk, sm.d, lane, r2);
        float av = rscatter(r2, lane);
        u_broadcast(sm, lane, w, rg, av, u2);
        gphase(Apk, u2, sm, lane, w);
        __syncthreads();
        int slot = ground & 1;
        float gj = g_exchange(sm, t, lane, w, slot,
                              slot ? gbar_rem1 : gbar_rem0,
                              slot ? gbuf_rem1 : gbuf_rem0);
        float wj = 0.f;
        if (t < Nn) {
            mbar_wait(slot ? gbar_loc1 : gbar_loc0, (uint32_t)((ground >> 1) & 1));
            wj = gj + sm.gbuf[slot][t];
        }
        ground++;
        float s = reduce_sum(sm.red, t, wj * wj);
        if (t < Nn) sm.d[t] = wj / (sqrtf(s) + 1e-12f);
        __syncthreads();
    }

    // ================= eta =================
    float eta;
    {
        rphase_fma(Apk, sm.d, lane, r2);
        float av = rscatter(r2, lane);
        float ss = ((lane & 3) == 0) ? av * av : 0.f;
        float sown = reduce_sum(sm.red, t, ss);
        int slot = sround & 1;
        if (t == 0) {
            st_remote_f32(speer_rem + (uint32_t)(slot * 4), sown);
            mbar_arrive_remote(sbar_rem);
        }
        mbar_wait(sbar_loc, (uint32_t)(sround & 1));
        sround++;
        eta = 1.0f / ((sown + sm.speer[slot]) + RHO_C);
    }

    // ================= K-step UVP =================
    for (int it = 0; it < KITERS; it++) {
        rphase_fma(Apk, sm.x, lane, r2);
        float r = rscatter(r2, lane);
        float uval = fmaxf(r - bt_own, 0.f);
        u_broadcast(sm, lane, w, rg, uval, u2);
        gphase(Apk, u2, sm, lane, w);
        __syncthreads();
        int slot = ground & 1;
        float gj = g_exchange(sm, t, lane, w, slot,
                              slot ? gbar_rem1 : gbar_rem0,
                              slot ? gbuf_rem1 : gbuf_rem0);
        if (t < Nn) {
            mbar_wait(slot ? gbar_loc1 : gbar_loc0, (uint32_t)((ground >> 1) & 1));
            sm.x[t] = sm.x[t] - eta * (gj + sm.gbuf[slot][t]);
        }
        ground++;
        __syncthreads();
    }

    // ================= stage 2: gate + alpha =================
    rphase_fma(Apk, sm.x, lane, r2);
    const float ax_own = rscatter(r2, lane);
    float vm = fmaxf(ax_own - bw_own, 0.f);
    float mvown = reduce_max(sm.red, t, vm);     // dup lanes idempotent
    float maxviol;
    {
        int slot = sround & 1;
        if (t == 0) {
            st_remote_f32(speer_rem + (uint32_t)(slot * 4), mvown);
            mbar_arrive_remote(sbar_rem);
        }
        mbar_wait(sbar_loc, (uint32_t)(sround & 1));
        sround++;
        maxviol = fmaxf(mvown, sm.speer[slot]);
    }
    const bool do_alpha = (maxviol <= FEAS_TOL);

    if (t < Nn) sm.d[t] = sm.x0[t] - sm.x[t];
    __syncthreads();
    rphase_fma(Apk, sm.d, lane, r2);
    const float ad_own = rscatter(r2, lane);
    float aown = (ad_own > 0.f) ? (bw_own - ax_own) / (ad_own + 1e-12f) : INFINITY;
    float amin = reduce_min(sm.red, t, aown);    // dup lanes idempotent
    float alpha;
    {
        int slot = sround & 1;
        if (t == 0) {
            st_remote_f32(speer_rem + (uint32_t)(slot * 4), amin);
            mbar_arrive_remote(sbar_rem);
        }
        mbar_wait(sbar_loc, (uint32_t)(sround & 1));
        sround++;
        alpha = fminf(amin, sm.speer[slot]);
    }
    if (!isfinite(alpha)) alpha = 1.0f;
    alpha = fminf(fmaxf(alpha - EPS_IN, 0.f), 1.f);

    if (rank == 0 && t < Nn) {
        float o = do_alpha ? (sm.x[t] + alpha * sm.d[t]) : sm.x[t];
        out_g[(size_t)prob * Nn + t] = o;
    }

    cluster_sync();   // no CTA exits while peer traffic may be in flight
}

extern "C" void kernel_launch(void* const* d_in, const int* in_sizes, int n_in,
                              void* d_out, int out_size) {
    const float* x = (const float*)d_in[0];
    const float* A = (const float*)d_in[1];
    const float* b = (const float*)d_in[2];
    float* out = (float*)d_out;

    const int nprob = in_sizes[0] / Nn;   // B*S
    cudaFuncSetAttribute(proj_kernel, cudaFuncAttributeMaxDynamicSharedMemorySize,
                         (int)sizeof(Smem));
    proj_kernel<<<nprob * 2, NTH, sizeof(Smem)>>>(x, A, b, out);
}